// round 1
// baseline (speedup 1.0000x reference)
#include <cuda_runtime.h>
#include <math.h>

// ---------------------------------------------------------------------------
// Problem constants
// ---------------------------------------------------------------------------
#define BB 8
#define TT 1024
#define DD 1024
#define HH 16
#define HD 64
#define FF 4096
#define MROWS (BB * TT)          // 8192
#define LN_EPS 1e-5f

// ---------------------------------------------------------------------------
// Scratch (allocation-free rule: __device__ globals)
// ---------------------------------------------------------------------------
__device__ float g_hln1[MROWS * DD];
__device__ float g_q[MROWS * DD];
__device__ float g_k[MROWS * DD];
__device__ float g_v[MROWS * DD];
__device__ float g_ctx[MROWS * DD];
__device__ float g_h[MROWS * DD];
__device__ float g_h2[MROWS * DD];
__device__ float g_ff[MROWS * FF];

// ---------------------------------------------------------------------------
// LayerNorm (torch-style: unbiased variance, ddof=1)
// one block per row of 1024, 256 threads, float4 I/O
// ---------------------------------------------------------------------------
__global__ void ln_kernel(const float* __restrict__ src,
                          const float* __restrict__ gamma,
                          const float* __restrict__ beta,
                          float* __restrict__ dst)
{
    const int row = blockIdx.x;
    const int tid = threadIdx.x;
    const float4* in4 = reinterpret_cast<const float4*>(src + (size_t)row * DD);
    float4* out4 = reinterpret_cast<float4*>(dst + (size_t)row * DD);
    const float4* g4 = reinterpret_cast<const float4*>(gamma);
    const float4* b4 = reinterpret_cast<const float4*>(beta);

    float4 x = in4[tid];
    float s  = x.x + x.y + x.z + x.w;
    float ss = x.x * x.x + x.y * x.y + x.z * x.z + x.w * x.w;

    // warp reduce
    for (int o = 16; o; o >>= 1) {
        s  += __shfl_xor_sync(0xffffffffu, s, o);
        ss += __shfl_xor_sync(0xffffffffu, ss, o);
    }
    __shared__ float rs[8], rss[8];
    __shared__ float smean, srstd;
    const int warp = tid >> 5, lane = tid & 31;
    if (lane == 0) { rs[warp] = s; rss[warp] = ss; }
    __syncthreads();
    if (warp == 0) {
        float a = (lane < 8) ? rs[lane] : 0.0f;
        float b = (lane < 8) ? rss[lane] : 0.0f;
        for (int o = 4; o; o >>= 1) {
            a += __shfl_xor_sync(0xffffffffu, a, o);
            b += __shfl_xor_sync(0xffffffffu, b, o);
        }
        if (lane == 0) {
            float mean = a * (1.0f / DD);
            float var  = (b - (float)DD * mean * mean) * (1.0f / (DD - 1));
            smean = mean;
            srstd = rsqrtf(var + LN_EPS);
        }
    }
    __syncthreads();
    const float mean = smean, rstd = srstd;
    float4 gv = g4[tid], bv = b4[tid];
    float4 o;
    o.x = (x.x - mean) * rstd * gv.x + bv.x;
    o.y = (x.y - mean) * rstd * gv.y + bv.y;
    o.z = (x.z - mean) * rstd * gv.z + bv.z;
    o.w = (x.w - mean) * rstd * gv.w + bv.w;
    out4[tid] = o;
}

// ---------------------------------------------------------------------------
// SGEMM: C[M,N] = A[M,K] @ B[K,N] + bias  (+ epilogue)
// MODE 0: +bias
// MODE 1: gelu(acc + bias)   (exact erf gelu)
// MODE 2: acc + bias + Res[m,n]
// 128x128x8 tile, 256 threads, 8x8 per-thread micro-tile.
// Requires M%128==0, N%128==0, K%8==0 (true for all uses here).
// ---------------------------------------------------------------------------
template <int MODE>
__global__ __launch_bounds__(256, 2)
void sgemm_kernel(const float* __restrict__ A,
                  const float* __restrict__ B,
                  const float* __restrict__ bias,
                  float* __restrict__ C,
                  const float* __restrict__ Res,
                  int M, int N, int K)
{
    __shared__ float As[8][128];
    __shared__ float Bs[8][128];

    const int tid = threadIdx.x;
    const int bx = blockIdx.x;   // N tile
    const int by = blockIdx.y;   // M tile

    const int tx = tid & 15;     // 0..15  -> n micro
    const int ty = tid >> 4;     // 0..15  -> m micro

    // A load mapping: thread t loads float4 at (row = t/2, k4 = (t%2)*4)
    const int a_row = tid >> 1;
    const int a_k4  = (tid & 1) << 2;
    // B load mapping: thread t loads float4 at (k = t/32, n4 = (t%32)*4)
    const int b_k   = tid >> 5;
    const int b_n4  = (tid & 31) << 2;

    const float* Ap = A + (size_t)(by * 128 + a_row) * K + a_k4;
    const float* Bp = B + (size_t)b_k * N + bx * 128 + b_n4;

    float acc[8][8];
#pragma unroll
    for (int i = 0; i < 8; i++)
#pragma unroll
        for (int j = 0; j < 8; j++) acc[i][j] = 0.0f;

    for (int k0 = 0; k0 < K; k0 += 8) {
        __syncthreads();
        float4 av = *reinterpret_cast<const float4*>(Ap + k0);
        As[a_k4 + 0][a_row] = av.x;
        As[a_k4 + 1][a_row] = av.y;
        As[a_k4 + 2][a_row] = av.z;
        As[a_k4 + 3][a_row] = av.w;
        float4 bv = *reinterpret_cast<const float4*>(Bp + (size_t)k0 * N);
        *reinterpret_cast<float4*>(&Bs[b_k][b_n4]) = bv;
        __syncthreads();

#pragma unroll
        for (int kk = 0; kk < 8; kk++) {
            float4 a0 = *reinterpret_cast<const float4*>(&As[kk][ty * 8]);
            float4 a1 = *reinterpret_cast<const float4*>(&As[kk][ty * 8 + 4]);
            float4 b0 = *reinterpret_cast<const float4*>(&Bs[kk][tx * 8]);
            float4 b1 = *reinterpret_cast<const float4*>(&Bs[kk][tx * 8 + 4]);
            float af[8] = {a0.x, a0.y, a0.z, a0.w, a1.x, a1.y, a1.z, a1.w};
            float bf[8] = {b0.x, b0.y, b0.z, b0.w, b1.x, b1.y, b1.z, b1.w};
#pragma unroll
            for (int i = 0; i < 8; i++)
#pragma unroll
                for (int j = 0; j < 8; j++)
                    acc[i][j] = fmaf(af[i], bf[j], acc[i][j]);
        }
    }

#pragma unroll
    for (int i = 0; i < 8; i++) {
        const int m = by * 128 + ty * 8 + i;
#pragma unroll
        for (int j = 0; j < 8; j++) {
            const int n = bx * 128 + tx * 8 + j;
            float val = acc[i][j] + bias[n];
            if (MODE == 1) {
                val = 0.5f * val * (1.0f + erff(val * 0.70710678118654752f));
            } else if (MODE == 2) {
                val += Res[(size_t)m * N + n];
            }
            C[(size_t)m * N + n] = val;
        }
    }
}

// ---------------------------------------------------------------------------
// Flash attention (fp32, no mask), HD=64, T=1024.
// grid: (B*H, T/16). 256 threads = 8 warps; each warp owns 2 query rows.
// K/V streamed through smem in 64-key tiles; online softmax in registers.
// ---------------------------------------------------------------------------
__global__ __launch_bounds__(256, 4)
void attn_kernel(const float* __restrict__ Q,
                 const float* __restrict__ K,
                 const float* __restrict__ V,
                 float* __restrict__ O)
{
    const int bh = blockIdx.x;
    const int b  = bh / HH;
    const int h  = bh % HH;
    const int q0 = blockIdx.y * 16;

    __shared__ float sQ[16][65];
    __shared__ float sK[64][65];
    __shared__ float sV[64][64];

    const int tid = threadIdx.x;
    const int warp = tid >> 5, lane = tid & 31;
    const size_t base = (size_t)b * TT * DD + (size_t)h * HD;

    // load Q tile (16 x 64)
    for (int i = tid; i < 16 * 64; i += 256) {
        int r = i >> 6, d = i & 63;
        sQ[r][d] = Q[base + (size_t)(q0 + r) * DD + d];
    }

    const int qa = warp * 2, qb = warp * 2 + 1;
    float m0 = -INFINITY, m1 = -INFINITY;
    float l0 = 0.0f, l1 = 0.0f;
    float acc00 = 0.0f, acc01 = 0.0f, acc10 = 0.0f, acc11 = 0.0f;
    const float scale = 0.125f;   // 1/sqrt(64)

    for (int t0 = 0; t0 < TT; t0 += 64) {
        __syncthreads();
        const float* Kb = K + base + (size_t)t0 * DD;
        const float* Vb = V + base + (size_t)t0 * DD;
        for (int i = tid; i < 64 * 16; i += 256) {
            int r = i >> 4, c = (i & 15) << 2;
            float4 kq = *reinterpret_cast<const float4*>(Kb + (size_t)r * DD + c);
            sK[r][c + 0] = kq.x; sK[r][c + 1] = kq.y;
            sK[r][c + 2] = kq.z; sK[r][c + 3] = kq.w;
            float4 vq = *reinterpret_cast<const float4*>(Vb + (size_t)r * DD + c);
            *reinterpret_cast<float4*>(&sV[r][c]) = vq;
        }
        __syncthreads();

        // scores: this warp's 2 queries vs 64 keys (2 keys / lane)
        float s00 = 0.0f, s01 = 0.0f, s10 = 0.0f, s11 = 0.0f;
#pragma unroll
        for (int d = 0; d < 64; d++) {
            float qv0 = sQ[qa][d], qv1 = sQ[qb][d];
            float k0v = sK[lane][d], k1v = sK[lane + 32][d];
            s00 = fmaf(qv0, k0v, s00);
            s01 = fmaf(qv0, k1v, s01);
            s10 = fmaf(qv1, k0v, s10);
            s11 = fmaf(qv1, k1v, s11);
        }
        s00 *= scale; s01 *= scale; s10 *= scale; s11 *= scale;

        float mx0 = fmaxf(s00, s01), mx1 = fmaxf(s10, s11);
        for (int o = 16; o; o >>= 1) {
            mx0 = fmaxf(mx0, __shfl_xor_sync(0xffffffffu, mx0, o));
            mx1 = fmaxf(mx1, __shfl_xor_sync(0xffffffffu, mx1, o));
        }
        const float nm0 = fmaxf(m0, mx0), nm1 = fmaxf(m1, mx1);
        const float c0 = __expf(m0 - nm0), c1 = __expf(m1 - nm1);
        const float p00 = __expf(s00 - nm0), p01 = __expf(s01 - nm0);
        const float p10 = __expf(s10 - nm1), p11 = __expf(s11 - nm1);
        float ls0 = p00 + p01, ls1 = p10 + p11;
        for (int o = 16; o; o >>= 1) {
            ls0 += __shfl_xor_sync(0xffffffffu, ls0, o);
            ls1 += __shfl_xor_sync(0xffffffffu, ls1, o);
        }
        l0 = l0 * c0 + ls0;
        l1 = l1 * c1 + ls1;
        acc00 *= c0; acc01 *= c0; acc10 *= c1; acc11 *= c1;
        m0 = nm0; m1 = nm1;

        // ctx accumulation: broadcast p_j from owning lane, FMA with V row j
#pragma unroll
        for (int j = 0; j < 64; j++) {
            const int src = j & 31;
            float pj0 = __shfl_sync(0xffffffffu, (j < 32) ? p00 : p01, src);
            float pj1 = __shfl_sync(0xffffffffu, (j < 32) ? p10 : p11, src);
            float v0 = sV[j][lane], v1 = sV[j][lane + 32];
            acc00 = fmaf(pj0, v0, acc00);
            acc01 = fmaf(pj0, v1, acc01);
            acc10 = fmaf(pj1, v0, acc10);
            acc11 = fmaf(pj1, v1, acc11);
        }
    }

    const float inv0 = 1.0f / l0, inv1 = 1.0f / l1;
    const size_t oa = base + (size_t)(q0 + qa) * DD;
    const size_t ob = base + (size_t)(q0 + qb) * DD;
    O[oa + lane]      = acc00 * inv0;
    O[oa + lane + 32] = acc01 * inv0;
    O[ob + lane]      = acc10 * inv1;
    O[ob + lane + 32] = acc11 * inv1;
}

// ---------------------------------------------------------------------------
// Launch
// ---------------------------------------------------------------------------
static float* sym(const void* symbol)
{
    void* p = nullptr;
    cudaGetSymbolAddress(&p, symbol);
    return reinterpret_cast<float*>(p);
}

extern "C" void kernel_launch(void* const* d_in, const int* in_sizes, int n_in,
                              void* d_out, int out_size)
{
    const float* x  = (const float*)d_in[0];
    const float* Wq = (const float*)d_in[1];  const float* bq = (const float*)d_in[2];
    const float* Wk = (const float*)d_in[3];  const float* bk = (const float*)d_in[4];
    const float* Wv = (const float*)d_in[5];  const float* bv = (const float*)d_in[6];
    const float* Wo = (const float*)d_in[7];  const float* bo = (const float*)d_in[8];
    const float* W1 = (const float*)d_in[9];  const float* b1 = (const float*)d_in[10];
    const float* W2 = (const float*)d_in[11]; const float* b2 = (const float*)d_in[12];
    const float* g1 = (const float*)d_in[13]; const float* be1 = (const float*)d_in[14];
    const float* g2 = (const float*)d_in[15]; const float* be2 = (const float*)d_in[16];
    float* out = (float*)d_out;

    float* hln1 = sym(g_hln1);
    float* qb   = sym(g_q);
    float* kb   = sym(g_k);
    float* vb   = sym(g_v);
    float* ctx  = sym(g_ctx);
    float* hb   = sym(g_h);
    float* h2b  = sym(g_h2);
    float* ffb  = sym(g_ff);

    // 1. LN1
    ln_kernel<<<MROWS, 256>>>(x, g1, be1, hln1);

    // 2. QKV projections
    {
        dim3 grid(DD / 128, MROWS / 128);
        sgemm_kernel<0><<<grid, 256>>>(hln1, Wq, bq, qb, nullptr, MROWS, DD, DD);
        sgemm_kernel<0><<<grid, 256>>>(hln1, Wk, bk, kb, nullptr, MROWS, DD, DD);
        sgemm_kernel<0><<<grid, 256>>>(hln1, Wv, bv, vb, nullptr, MROWS, DD, DD);
    }

    // 3. attention
    {
        dim3 grid(BB * HH, TT / 16);
        attn_kernel<<<grid, 256>>>(qb, kb, vb, ctx);
    }

    // 4. output projection + residual (h = hln1 + ctx@Wo + bo)
    {
        dim3 grid(DD / 128, MROWS / 128);
        sgemm_kernel<2><<<grid, 256>>>(ctx, Wo, bo, hb, hln1, MROWS, DD, DD);
    }

    // 5. LN2
    ln_kernel<<<MROWS, 256>>>(hb, g2, be2, h2b);

    // 6. FFN up + exact GELU
    {
        dim3 grid(FF / 128, MROWS / 128);
        sgemm_kernel<1><<<grid, 256>>>(h2b, W1, b1, ffb, nullptr, MROWS, FF, DD);
    }

    // 7. FFN down + bias + residual (out = h2 + ff@W2 + b2)
    {
        dim3 grid(DD / 128, MROWS / 128);
        sgemm_kernel<2><<<grid, 256>>>(ffb, W2, b2, out, h2b, MROWS, DD, FF);
    }
}

// round 3
// speedup vs baseline: 2.1340x; 2.1340x over previous
#include <cuda_runtime.h>
#include <math.h>
#include <stdint.h>

// ---------------------------------------------------------------------------
// Problem constants
// ---------------------------------------------------------------------------
#define BB 8
#define TT 1024
#define DD 1024
#define HH 16
#define HD 64
#define FF 4096
#define MROWS (BB * TT)          // 8192
#define LN_EPS 1e-5f

// ---------------------------------------------------------------------------
// Scratch (__device__ globals; allocation-free rule)
// ---------------------------------------------------------------------------
__device__ float g_hln1 [MROWS * DD];
__device__ float g_hln1t[MROWS * DD];
__device__ float g_q    [MROWS * DD];
__device__ float g_k    [MROWS * DD];
__device__ float g_v    [MROWS * DD];
__device__ float g_ctx  [MROWS * DD];
__device__ float g_h    [MROWS * DD];
__device__ float g_h2   [MROWS * DD];
__device__ float g_h2t  [MROWS * DD];
__device__ float g_ff   [MROWS * FF];
__device__ float g_WqT  [DD * DD];
__device__ float g_WkT  [DD * DD];
__device__ float g_WvT  [DD * DD];
__device__ float g_WoT  [DD * DD];
__device__ float g_W1T  [FF * DD];
__device__ float g_W2T  [DD * FF];

// ---------------------------------------------------------------------------
// Helpers
// ---------------------------------------------------------------------------
__device__ __forceinline__ uint32_t smem_u32(const void* p) {
    uint32_t a;
    asm("{ .reg .u64 t; cvta.to.shared.u64 t, %1; cvt.u32.u64 %0, t; }"
        : "=r"(a) : "l"(p));
    return a;
}

__device__ __forceinline__ float rn_tf32(float x) {
    float y;
    asm("cvt.rna.tf32.f32 %0, %1;" : "=f"(y) : "f"(x));
    return y;
}

__device__ __forceinline__ void cp_async16(uint32_t saddr, const void* gaddr) {
    asm volatile("cp.async.cg.shared.global [%0], [%1], 16;\n"
                 :: "r"(saddr), "l"(gaddr) : "memory");
}
#define CP_COMMIT() asm volatile("cp.async.commit_group;\n" ::: "memory")

__device__ __forceinline__ void mma_tf32(float c[4], const uint32_t a[4],
                                         const uint32_t b[2]) {
    asm volatile(
        "mma.sync.aligned.m16n8k8.row.col.f32.tf32.tf32.f32 "
        "{%0,%1,%2,%3}, {%4,%5,%6,%7}, {%8,%9}, {%0,%1,%2,%3};"
        : "+f"(c[0]), "+f"(c[1]), "+f"(c[2]), "+f"(c[3])
        : "r"(a[0]), "r"(a[1]), "r"(a[2]), "r"(a[3]),
          "r"(b[0]), "r"(b[1]));
}

// ---------------------------------------------------------------------------
// Weight transpose + round-to-nearest tf32: out[N,K] = rn(in[K,N]^T)
// ---------------------------------------------------------------------------
__global__ void transpose_rn_kernel(const float* __restrict__ in,
                                    float* __restrict__ out, int K, int N)
{
    __shared__ float t[32][33];
    const int n0 = blockIdx.x * 32, k0 = blockIdx.y * 32;
    for (int i = threadIdx.y; i < 32; i += 8)
        t[i][threadIdx.x] = in[(size_t)(k0 + i) * N + n0 + threadIdx.x];
    __syncthreads();
    for (int i = threadIdx.y; i < 32; i += 8)
        out[(size_t)(n0 + i) * K + k0 + threadIdx.x] = rn_tf32(t[threadIdx.x][i]);
}

// ---------------------------------------------------------------------------
// LayerNorm (unbiased var, ddof=1), dual output: fp32 + tf32-rounded
// ---------------------------------------------------------------------------
__global__ void ln_kernel(const float* __restrict__ src,
                          const float* __restrict__ gamma,
                          const float* __restrict__ beta,
                          float* __restrict__ dst,
                          float* __restrict__ dstt)
{
    const int row = blockIdx.x;
    const int tid = threadIdx.x;
    const float4* in4 = reinterpret_cast<const float4*>(src + (size_t)row * DD);
    float4* out4  = reinterpret_cast<float4*>(dst  + (size_t)row * DD);
    float4* outt4 = reinterpret_cast<float4*>(dstt + (size_t)row * DD);
    const float4* g4 = reinterpret_cast<const float4*>(gamma);
    const float4* b4 = reinterpret_cast<const float4*>(beta);

    float4 x = in4[tid];
    float s  = x.x + x.y + x.z + x.w;
    float ss = x.x * x.x + x.y * x.y + x.z * x.z + x.w * x.w;
    for (int o = 16; o; o >>= 1) {
        s  += __shfl_xor_sync(0xffffffffu, s, o);
        ss += __shfl_xor_sync(0xffffffffu, ss, o);
    }
    __shared__ float rs[8], rss[8];
    __shared__ float smean, srstd;
    const int warp = tid >> 5, lane = tid & 31;
    if (lane == 0) { rs[warp] = s; rss[warp] = ss; }
    __syncthreads();
    if (warp == 0) {
        float a = (lane < 8) ? rs[lane] : 0.0f;
        float b = (lane < 8) ? rss[lane] : 0.0f;
        for (int o = 4; o; o >>= 1) {
            a += __shfl_xor_sync(0xffffffffu, a, o);
            b += __shfl_xor_sync(0xffffffffu, b, o);
        }
        if (lane == 0) {
            float mean = a * (1.0f / DD);
            float var  = (b - (float)DD * mean * mean) * (1.0f / (DD - 1));
            smean = mean;
            srstd = rsqrtf(var + LN_EPS);
        }
    }
    __syncthreads();
    const float mean = smean, rstd = srstd;
    float4 gv = g4[tid], bv = b4[tid];
    float4 o;
    o.x = (x.x - mean) * rstd * gv.x + bv.x;
    o.y = (x.y - mean) * rstd * gv.y + bv.y;
    o.z = (x.z - mean) * rstd * gv.z + bv.z;
    o.w = (x.w - mean) * rstd * gv.w + bv.w;
    out4[tid] = o;
    float4 ot;
    ot.x = rn_tf32(o.x); ot.y = rn_tf32(o.y);
    ot.z = rn_tf32(o.z); ot.w = rn_tf32(o.w);
    outt4[tid] = ot;
}

// ---------------------------------------------------------------------------
// tf32 mma.sync GEMM: C[M,N] = A[M,K] @ B^T (B stored [N,K] K-major) + bias
// MODE 0: +bias    MODE 1: rn_tf32(gelu(acc+bias))    MODE 2: +bias+Res
// 128x128 tile, K chunks of 32, 2-stage cp.async double buffer.
// 8 warps as 4(m) x 2(n); warp tile 32x64; mma m16n8k8.
// Smem rows padded to 36 floats -> conflict-free fragment LDS.
// ---------------------------------------------------------------------------
#define TSTRIDE 36
#define TILE_BYTES (128 * TSTRIDE * 4)          // 18432 per operand
#define STAGE_BYTES (2 * TILE_BYTES)            // 36864 (A then B)
#define GSMEM_BYTES (2 * STAGE_BYTES)           // 73728

template <int MODE>
__global__ __launch_bounds__(256)
void gemm_mma(const float* __restrict__ A, const float* __restrict__ B,
              const float* __restrict__ bias, float* __restrict__ C,
              const float* __restrict__ Res, int M, int N, int K)
{
    extern __shared__ char dynsmem[];
    const int tid = threadIdx.x;
    const int wid = tid >> 5, lane = tid & 31;
    const int bx = blockIdx.x, by = blockIdx.y;

    const int warp_m = (wid & 3) * 32;
    const int warp_n = (wid >> 2) * 64;
    const int lr = lane >> 2;      // 0..7
    const int lc = lane & 3;       // 0..3

    const uint32_t sbase = smem_u32(dynsmem);

    // global load plan: 4 float4 per thread per operand per stage
    const int g_r  = tid >> 3;       // 0..31 (+p*32)
    const int g_c4 = (tid & 7) << 2; // float offset 0,4,...,28
    const float* gA = A + (size_t)(by * 128 + g_r) * K + g_c4;
    const float* gB = B + (size_t)(bx * 128 + g_r) * K + g_c4;
    const uint32_t s_off = (uint32_t)((g_r * TSTRIDE + g_c4) * 4);

    const int NITER = K >> 5;

    auto stage = [&](int s) {
        const uint32_t base = sbase + (uint32_t)(s & 1) * STAGE_BYTES;
        const int k0 = s << 5;
#pragma unroll
        for (int p = 0; p < 4; p++) {
            const uint32_t rowoff = (uint32_t)(p * 32 * TSTRIDE * 4);
            const size_t goff = (size_t)(p * 32) * K + k0;
            cp_async16(base + s_off + rowoff, gA + goff);
            cp_async16(base + TILE_BYTES + s_off + rowoff, gB + goff);
        }
        CP_COMMIT();
    };

    float c[2][8][4];
#pragma unroll
    for (int mt = 0; mt < 2; mt++)
#pragma unroll
        for (int nt = 0; nt < 8; nt++)
#pragma unroll
            for (int r = 0; r < 4; r++) c[mt][nt][r] = 0.0f;

    stage(0);
    if (NITER > 1) stage(1);

    for (int i = 0; i < NITER; i++) {
        if (i + 2 <= NITER - 1 || (i + 1 <= NITER - 1))
            asm volatile("cp.async.wait_group 1;\n" ::: "memory");
        else
            asm volatile("cp.async.wait_group 0;\n" ::: "memory");
        __syncthreads();

        const uint32_t* As = reinterpret_cast<const uint32_t*>(
            dynsmem + (size_t)(i & 1) * STAGE_BYTES);
        const uint32_t* Bs = reinterpret_cast<const uint32_t*>(
            dynsmem + (size_t)(i & 1) * STAGE_BYTES + TILE_BYTES);

#pragma unroll
        for (int kk = 0; kk < 32; kk += 8) {
            uint32_t a[2][4];
#pragma unroll
            for (int mt = 0; mt < 2; mt++) {
                const int r0 = warp_m + mt * 16 + lr;
                a[mt][0] = As[r0 * TSTRIDE + kk + lc];
                a[mt][1] = As[(r0 + 8) * TSTRIDE + kk + lc];
                a[mt][2] = As[r0 * TSTRIDE + kk + lc + 4];
                a[mt][3] = As[(r0 + 8) * TSTRIDE + kk + lc + 4];
            }
            uint32_t b[8][2];
#pragma unroll
            for (int nt = 0; nt < 8; nt++) {
                const int n0 = warp_n + nt * 8 + lr;
                b[nt][0] = Bs[n0 * TSTRIDE + kk + lc];
                b[nt][1] = Bs[n0 * TSTRIDE + kk + lc + 4];
            }
#pragma unroll
            for (int mt = 0; mt < 2; mt++)
#pragma unroll
                for (int nt = 0; nt < 8; nt++)
                    mma_tf32(c[mt][nt], a[mt], b[nt]);
        }

        if (i + 2 < NITER) {
            __syncthreads();
            stage(i + 2);
        }
    }

    // epilogue
    const float inv_s2 = 0.70710678118654752f;
#pragma unroll
    for (int mt = 0; mt < 2; mt++) {
#pragma unroll
        for (int rh = 0; rh < 2; rh++) {   // row half: +0 / +8
            const int m = by * 128 + warp_m + mt * 16 + lr + rh * 8;
#pragma unroll
            for (int nt = 0; nt < 8; nt++) {
                const int n = bx * 128 + warp_n + nt * 8 + 2 * lc;
                float v0 = c[mt][nt][rh * 2 + 0] + bias[n];
                float v1 = c[mt][nt][rh * 2 + 1] + bias[n + 1];
                if (MODE == 1) {
                    v0 = rn_tf32(0.5f * v0 * (1.0f + erff(v0 * inv_s2)));
                    v1 = rn_tf32(0.5f * v1 * (1.0f + erff(v1 * inv_s2)));
                } else if (MODE == 2) {
                    float2 rv = *reinterpret_cast<const float2*>(
                        Res + (size_t)m * N + n);
                    v0 += rv.x; v1 += rv.y;
                }
                float2 o2 = make_float2(v0, v1);
                *reinterpret_cast<float2*>(C + (size_t)m * N + n) = o2;
            }
        }
    }
}

// ---------------------------------------------------------------------------
// Flash attention (fp32), HD=64, T=1024; outputs rn_tf32 for the Wo GEMM
// ---------------------------------------------------------------------------
__global__ __launch_bounds__(256, 4)
void attn_kernel(const float* __restrict__ Q,
                 const float* __restrict__ K,
                 const float* __restrict__ V,
                 float* __restrict__ O)
{
    const int bh = blockIdx.x;
    const int b  = bh / HH;
    const int h  = bh % HH;
    const int q0 = blockIdx.y * 16;

    __shared__ float sQ[16][65];
    __shared__ float sK[64][65];
    __shared__ float sV[64][64];

    const int tid = threadIdx.x;
    const int warp = tid >> 5, lane = tid & 31;
    const size_t base = (size_t)b * TT * DD + (size_t)h * HD;

    for (int i = tid; i < 16 * 64; i += 256) {
        int r = i >> 6, d = i & 63;
        sQ[r][d] = Q[base + (size_t)(q0 + r) * DD + d];
    }

    const int qa = warp * 2, qb = warp * 2 + 1;
    float m0 = -INFINITY, m1 = -INFINITY;
    float l0 = 0.0f, l1 = 0.0f;
    float acc00 = 0.0f, acc01 = 0.0f, acc10 = 0.0f, acc11 = 0.0f;
    const float scale = 0.125f;

    for (int t0 = 0; t0 < TT; t0 += 64) {
        __syncthreads();
        const float* Kb = K + base + (size_t)t0 * DD;
        const float* Vb = V + base + (size_t)t0 * DD;
        for (int i = tid; i < 64 * 16; i += 256) {
            int r = i >> 4, c = (i & 15) << 2;
            float4 kq = *reinterpret_cast<const float4*>(Kb + (size_t)r * DD + c);
            sK[r][c + 0] = kq.x; sK[r][c + 1] = kq.y;
            sK[r][c + 2] = kq.z; sK[r][c + 3] = kq.w;
            float4 vq = *reinterpret_cast<const float4*>(Vb + (size_t)r * DD + c);
            *reinterpret_cast<float4*>(&sV[r][c]) = vq;
        }
        __syncthreads();

        float s00 = 0.0f, s01 = 0.0f, s10 = 0.0f, s11 = 0.0f;
#pragma unroll
        for (int d = 0; d < 64; d++) {
            float qv0 = sQ[qa][d], qv1 = sQ[qb][d];
            float k0v = sK[lane][d], k1v = sK[lane + 32][d];
            s00 = fmaf(qv0, k0v, s00);
            s01 = fmaf(qv0, k1v, s01);
            s10 = fmaf(qv1, k0v, s10);
            s11 = fmaf(qv1, k1v, s11);
        }
        s00 *= scale; s01 *= scale; s10 *= scale; s11 *= scale;

        float mx0 = fmaxf(s00, s01), mx1 = fmaxf(s10, s11);
        for (int o = 16; o; o >>= 1) {
            mx0 = fmaxf(mx0, __shfl_xor_sync(0xffffffffu, mx0, o));
            mx1 = fmaxf(mx1, __shfl_xor_sync(0xffffffffu, mx1, o));
        }
        const float nm0 = fmaxf(m0, mx0), nm1 = fmaxf(m1, mx1);
        const float c0 = __expf(m0 - nm0), c1 = __expf(m1 - nm1);
        const float p00 = __expf(s00 - nm0), p01 = __expf(s01 - nm0);
        const float p10 = __expf(s10 - nm1), p11 = __expf(s11 - nm1);
        float ls0 = p00 + p01, ls1 = p10 + p11;
        for (int o = 16; o; o >>= 1) {
            ls0 += __shfl_xor_sync(0xffffffffu, ls0, o);
            ls1 += __shfl_xor_sync(0xffffffffu, ls1, o);
        }
        l0 = l0 * c0 + ls0;
        l1 = l1 * c1 + ls1;
        acc00 *= c0; acc01 *= c0; acc10 *= c1; acc11 *= c1;
        m0 = nm0; m1 = nm1;

#pragma unroll
        for (int j = 0; j < 64; j++) {
            const int src = j & 31;
            float pj0 = __shfl_sync(0xffffffffu, (j < 32) ? p00 : p01, src);
            float pj1 = __shfl_sync(0xffffffffu, (j < 32) ? p10 : p11, src);
            float v0 = sV[j][lane], v1 = sV[j][lane + 32];
            acc00 = fmaf(pj0, v0, acc00);
            acc01 = fmaf(pj0, v1, acc01);
            acc10 = fmaf(pj1, v0, acc10);
            acc11 = fmaf(pj1, v1, acc11);
        }
    }

    const float inv0 = 1.0f / l0, inv1 = 1.0f / l1;
    const size_t oa = base + (size_t)(q0 + qa) * DD;
    const size_t ob = base + (size_t)(q0 + qb) * DD;
    O[oa + lane]      = rn_tf32(acc00 * inv0);
    O[oa + lane + 32] = rn_tf32(acc01 * inv0);
    O[ob + lane]      = rn_tf32(acc10 * inv1);
    O[ob + lane + 32] = rn_tf32(acc11 * inv1);
}

// ---------------------------------------------------------------------------
// Launch
// ---------------------------------------------------------------------------
static float* sym(const void* symbol)
{
    void* p = nullptr;
    cudaGetSymbolAddress(&p, symbol);
    return reinterpret_cast<float*>(p);
}

extern "C" void kernel_launch(void* const* d_in, const int* in_sizes, int n_in,
                              void* d_out, int out_size)
{
    const float* x  = (const float*)d_in[0];
    const float* Wq = (const float*)d_in[1];  const float* bq = (const float*)d_in[2];
    const float* Wk = (const float*)d_in[3];  const float* bk = (const float*)d_in[4];
    const float* Wv = (const float*)d_in[5];  const float* bv = (const float*)d_in[6];
    const float* Wo = (const float*)d_in[7];  const float* bo = (const float*)d_in[8];
    const float* W1 = (const float*)d_in[9];  const float* b1 = (const float*)d_in[10];
    const float* W2 = (const float*)d_in[11]; const float* b2 = (const float*)d_in[12];
    const float* g1 = (const float*)d_in[13]; const float* be1 = (const float*)d_in[14];
    const float* g2 = (const float*)d_in[15]; const float* be2 = (const float*)d_in[16];
    float* out = (float*)d_out;

    float* hln1  = sym(g_hln1);
    float* hln1t = sym(g_hln1t);
    float* qb    = sym(g_q);
    float* kb    = sym(g_k);
    float* vb    = sym(g_v);
    float* ctx   = sym(g_ctx);
    float* hb    = sym(g_h);
    float* h2b   = sym(g_h2);
    float* h2t   = sym(g_h2t);
    float* ffb   = sym(g_ff);
    float* WqT = sym(g_WqT); float* WkT = sym(g_WkT);
    float* WvT = sym(g_WvT); float* WoT = sym(g_WoT);
    float* W1T = sym(g_W1T); float* W2T = sym(g_W2T);

    cudaFuncSetAttribute(gemm_mma<0>, cudaFuncAttributeMaxDynamicSharedMemorySize, GSMEM_BYTES);
    cudaFuncSetAttribute(gemm_mma<1>, cudaFuncAttributeMaxDynamicSharedMemorySize, GSMEM_BYTES);
    cudaFuncSetAttribute(gemm_mma<2>, cudaFuncAttributeMaxDynamicSharedMemorySize, GSMEM_BYTES);

    // weight transposes (+ tf32 RN), B operands become [N,K] K-major
    {
        dim3 thr(32, 8);
        transpose_rn_kernel<<<dim3(DD / 32, DD / 32), thr>>>(Wq, WqT, DD, DD);
        transpose_rn_kernel<<<dim3(DD / 32, DD / 32), thr>>>(Wk, WkT, DD, DD);
        transpose_rn_kernel<<<dim3(DD / 32, DD / 32), thr>>>(Wv, WvT, DD, DD);
        transpose_rn_kernel<<<dim3(DD / 32, DD / 32), thr>>>(Wo, WoT, DD, DD);
        transpose_rn_kernel<<<dim3(FF / 32, DD / 32), thr>>>(W1, W1T, DD, FF);
        transpose_rn_kernel<<<dim3(DD / 32, FF / 32), thr>>>(W2, W2T, FF, DD);
    }

    // 1. LN1 (fp32 + tf32 copies)
    ln_kernel<<<MROWS, 256>>>(x, g1, be1, hln1, hln1t);

    // 2. QKV projections (tensor cores via mma.sync tf32)
    {
        dim3 grid(DD / 128, MROWS / 128);
        gemm_mma<0><<<grid, 256, GSMEM_BYTES>>>(hln1t, WqT, bq, qb, nullptr, MROWS, DD, DD);
        gemm_mma<0><<<grid, 256, GSMEM_BYTES>>>(hln1t, WkT, bk, kb, nullptr, MROWS, DD, DD);
        gemm_mma<0><<<grid, 256, GSMEM_BYTES>>>(hln1t, WvT, bv, vb, nullptr, MROWS, DD, DD);
    }

    // 3. attention (outputs tf32-rounded ctx)
    {
        dim3 grid(BB * HH, TT / 16);
        attn_kernel<<<grid, 256>>>(qb, kb, vb, ctx);
    }

    // 4. output projection + residual
    {
        dim3 grid(DD / 128, MROWS / 128);
        gemm_mma<2><<<grid, 256, GSMEM_BYTES>>>(ctx, WoT, bo, hb, hln1, MROWS, DD, DD);
    }

    // 5. LN2
    ln_kernel<<<MROWS, 256>>>(hb, g2, be2, h2b, h2t);

    // 6. FFN up + exact GELU (output tf32-rounded)
    {
        dim3 grid(FF / 128, MROWS / 128);
        gemm_mma<1><<<grid, 256, GSMEM_BYTES>>>(h2t, W1T, b1, ffb, nullptr, MROWS, FF, DD);
    }

    // 7. FFN down + bias + residual -> out
    {
        dim3 grid(DD / 128, MROWS / 128);
        gemm_mma<2><<<grid, 256, GSMEM_BYTES>>>(ffb, W2T, b2, out, h2b, MROWS, DD, FF);
    }
}

// round 4
// speedup vs baseline: 3.8137x; 1.7872x over previous
#include <cuda_runtime.h>
#include <math.h>
#include <stdint.h>

// ---------------------------------------------------------------------------
// Problem constants
// ---------------------------------------------------------------------------
#define BB 8
#define TT 1024
#define DD 1024
#define HH 16
#define HD 64
#define FF 4096
#define MROWS (BB * TT)          // 8192
#define LN_EPS 1e-5f

// ---------------------------------------------------------------------------
// Scratch (__device__ globals; allocation-free rule)
// ---------------------------------------------------------------------------
__device__ float g_hln1 [MROWS * DD];
__device__ float g_hln1t[MROWS * DD];
__device__ float g_q    [MROWS * DD];
__device__ float g_k    [MROWS * DD];
__device__ float g_v    [MROWS * DD];
__device__ float g_ctx  [MROWS * DD];
__device__ float g_h    [MROWS * DD];
__device__ float g_h2   [MROWS * DD];
__device__ float g_h2t  [MROWS * DD];
__device__ float g_ff   [MROWS * FF];
__device__ float g_WqT  [DD * DD];
__device__ float g_WkT  [DD * DD];
__device__ float g_WvT  [DD * DD];
__device__ float g_WoT  [DD * DD];
__device__ float g_W1T  [FF * DD];
__device__ float g_W2T  [DD * FF];

// ---------------------------------------------------------------------------
// Helpers
// ---------------------------------------------------------------------------
__device__ __forceinline__ uint32_t smem_u32(const void* p) {
    uint32_t a;
    asm("{ .reg .u64 t; cvta.to.shared.u64 t, %1; cvt.u32.u64 %0, t; }"
        : "=r"(a) : "l"(p));
    return a;
}

__device__ __forceinline__ float rn_tf32(float x) {
    float y;
    asm("cvt.rna.tf32.f32 %0, %1;" : "=f"(y) : "f"(x));
    return y;
}

__device__ __forceinline__ void cp_async16(uint32_t saddr, const void* gaddr) {
    asm volatile("cp.async.cg.shared.global [%0], [%1], 16;\n"
                 :: "r"(saddr), "l"(gaddr) : "memory");
}
#define CP_COMMIT() asm volatile("cp.async.commit_group;\n" ::: "memory")

__device__ __forceinline__ void mma_tf32(float c[4], const uint32_t a[4],
                                         const uint32_t b[2]) {
    asm volatile(
        "mma.sync.aligned.m16n8k8.row.col.f32.tf32.tf32.f32 "
        "{%0,%1,%2,%3}, {%4,%5,%6,%7}, {%8,%9}, {%0,%1,%2,%3};"
        : "+f"(c[0]), "+f"(c[1]), "+f"(c[2]), "+f"(c[3])
        : "r"(a[0]), "r"(a[1]), "r"(a[2]), "r"(a[3]),
          "r"(b[0]), "r"(b[1]));
}

// ---------------------------------------------------------------------------
// Weight transpose + round-to-nearest tf32: out[N,K] = rn(in[K,N]^T)
// ---------------------------------------------------------------------------
__global__ void transpose_rn_kernel(const float* __restrict__ in,
                                    float* __restrict__ out, int K, int N)
{
    __shared__ float t[32][33];
    const int n0 = blockIdx.x * 32, k0 = blockIdx.y * 32;
    for (int i = threadIdx.y; i < 32; i += 8)
        t[i][threadIdx.x] = in[(size_t)(k0 + i) * N + n0 + threadIdx.x];
    __syncthreads();
    for (int i = threadIdx.y; i < 32; i += 8)
        out[(size_t)(n0 + i) * K + k0 + threadIdx.x] = rn_tf32(t[threadIdx.x][i]);
}

// ---------------------------------------------------------------------------
// LayerNorm (unbiased var, ddof=1), dual output: fp32 + tf32-rounded
// ---------------------------------------------------------------------------
__global__ void ln_kernel(const float* __restrict__ src,
                          const float* __restrict__ gamma,
                          const float* __restrict__ beta,
                          float* __restrict__ dst,
                          float* __restrict__ dstt)
{
    const int row = blockIdx.x;
    const int tid = threadIdx.x;
    const float4* in4 = reinterpret_cast<const float4*>(src + (size_t)row * DD);
    float4* out4  = reinterpret_cast<float4*>(dst  + (size_t)row * DD);
    float4* outt4 = reinterpret_cast<float4*>(dstt + (size_t)row * DD);
    const float4* g4 = reinterpret_cast<const float4*>(gamma);
    const float4* b4 = reinterpret_cast<const float4*>(beta);

    float4 x = in4[tid];
    float s  = x.x + x.y + x.z + x.w;
    float ss = x.x * x.x + x.y * x.y + x.z * x.z + x.w * x.w;
    for (int o = 16; o; o >>= 1) {
        s  += __shfl_xor_sync(0xffffffffu, s, o);
        ss += __shfl_xor_sync(0xffffffffu, ss, o);
    }
    __shared__ float rs[8], rss[8];
    __shared__ float smean, srstd;
    const int warp = tid >> 5, lane = tid & 31;
    if (lane == 0) { rs[warp] = s; rss[warp] = ss; }
    __syncthreads();
    if (warp == 0) {
        float a = (lane < 8) ? rs[lane] : 0.0f;
        float b = (lane < 8) ? rss[lane] : 0.0f;
        for (int o = 4; o; o >>= 1) {
            a += __shfl_xor_sync(0xffffffffu, a, o);
            b += __shfl_xor_sync(0xffffffffu, b, o);
        }
        if (lane == 0) {
            float mean = a * (1.0f / DD);
            float var  = (b - (float)DD * mean * mean) * (1.0f / (DD - 1));
            smean = mean;
            srstd = rsqrtf(var + LN_EPS);
        }
    }
    __syncthreads();
    const float mean = smean, rstd = srstd;
    float4 gv = g4[tid], bv = b4[tid];
    float4 o;
    o.x = (x.x - mean) * rstd * gv.x + bv.x;
    o.y = (x.y - mean) * rstd * gv.y + bv.y;
    o.z = (x.z - mean) * rstd * gv.z + bv.z;
    o.w = (x.w - mean) * rstd * gv.w + bv.w;
    out4[tid] = o;
    float4 ot;
    ot.x = rn_tf32(o.x); ot.y = rn_tf32(o.y);
    ot.z = rn_tf32(o.z); ot.w = rn_tf32(o.w);
    outt4[tid] = ot;
}

// ---------------------------------------------------------------------------
// tf32 mma.sync GEMM: C[M,N] = A[M,K] @ B^T (B stored [N,K] K-major) + bias
// MODE 0: +bias                MODE 1: rn_tf32(gelu(acc+bias))
// MODE 2: +bias+Res            MODE 3: rn_tf32(acc+bias)
// ---------------------------------------------------------------------------
#define TSTRIDE 36
#define TILE_BYTES (128 * TSTRIDE * 4)          // 18432 per operand
#define STAGE_BYTES (2 * TILE_BYTES)            // 36864 (A then B)
#define GSMEM_BYTES (2 * STAGE_BYTES)           // 73728

template <int MODE>
__global__ __launch_bounds__(256)
void gemm_mma(const float* __restrict__ A, const float* __restrict__ B,
              const float* __restrict__ bias, float* __restrict__ C,
              const float* __restrict__ Res, int M, int N, int K)
{
    extern __shared__ char dynsmem[];
    const int tid = threadIdx.x;
    const int wid = tid >> 5, lane = tid & 31;
    const int bx = blockIdx.x, by = blockIdx.y;

    const int warp_m = (wid & 3) * 32;
    const int warp_n = (wid >> 2) * 64;
    const int lr = lane >> 2;      // 0..7
    const int lc = lane & 3;       // 0..3

    const uint32_t sbase = smem_u32(dynsmem);

    const int g_r  = tid >> 3;
    const int g_c4 = (tid & 7) << 2;
    const float* gA = A + (size_t)(by * 128 + g_r) * K + g_c4;
    const float* gB = B + (size_t)(bx * 128 + g_r) * K + g_c4;
    const uint32_t s_off = (uint32_t)((g_r * TSTRIDE + g_c4) * 4);

    const int NITER = K >> 5;

    auto stage = [&](int s) {
        const uint32_t base = sbase + (uint32_t)(s & 1) * STAGE_BYTES;
        const int k0 = s << 5;
#pragma unroll
        for (int p = 0; p < 4; p++) {
            const uint32_t rowoff = (uint32_t)(p * 32 * TSTRIDE * 4);
            const size_t goff = (size_t)(p * 32) * K + k0;
            cp_async16(base + s_off + rowoff, gA + goff);
            cp_async16(base + TILE_BYTES + s_off + rowoff, gB + goff);
        }
        CP_COMMIT();
    };

    float c[2][8][4];
#pragma unroll
    for (int mt = 0; mt < 2; mt++)
#pragma unroll
        for (int nt = 0; nt < 8; nt++)
#pragma unroll
            for (int r = 0; r < 4; r++) c[mt][nt][r] = 0.0f;

    stage(0);
    if (NITER > 1) stage(1);

    for (int i = 0; i < NITER; i++) {
        if (i < NITER - 1)
            asm volatile("cp.async.wait_group 1;\n" ::: "memory");
        else
            asm volatile("cp.async.wait_group 0;\n" ::: "memory");
        __syncthreads();

        const uint32_t* As = reinterpret_cast<const uint32_t*>(
            dynsmem + (size_t)(i & 1) * STAGE_BYTES);
        const uint32_t* Bs = reinterpret_cast<const uint32_t*>(
            dynsmem + (size_t)(i & 1) * STAGE_BYTES + TILE_BYTES);

#pragma unroll
        for (int kk = 0; kk < 32; kk += 8) {
            uint32_t a[2][4];
#pragma unroll
            for (int mt = 0; mt < 2; mt++) {
                const int r0 = warp_m + mt * 16 + lr;
                a[mt][0] = As[r0 * TSTRIDE + kk + lc];
                a[mt][1] = As[(r0 + 8) * TSTRIDE + kk + lc];
                a[mt][2] = As[r0 * TSTRIDE + kk + lc + 4];
                a[mt][3] = As[(r0 + 8) * TSTRIDE + kk + lc + 4];
            }
            uint32_t b[8][2];
#pragma unroll
            for (int nt = 0; nt < 8; nt++) {
                const int n0 = warp_n + nt * 8 + lr;
                b[nt][0] = Bs[n0 * TSTRIDE + kk + lc];
                b[nt][1] = Bs[n0 * TSTRIDE + kk + lc + 4];
            }
#pragma unroll
            for (int mt = 0; mt < 2; mt++)
#pragma unroll
                for (int nt = 0; nt < 8; nt++)
                    mma_tf32(c[mt][nt], a[mt], b[nt]);
        }

        if (i + 2 < NITER) {
            __syncthreads();
            stage(i + 2);
        }
    }

    const float inv_s2 = 0.70710678118654752f;
#pragma unroll
    for (int mt = 0; mt < 2; mt++) {
#pragma unroll
        for (int rh = 0; rh < 2; rh++) {
            const int m = by * 128 + warp_m + mt * 16 + lr + rh * 8;
#pragma unroll
            for (int nt = 0; nt < 8; nt++) {
                const int n = bx * 128 + warp_n + nt * 8 + 2 * lc;
                float v0 = c[mt][nt][rh * 2 + 0] + bias[n];
                float v1 = c[mt][nt][rh * 2 + 1] + bias[n + 1];
                if (MODE == 1) {
                    v0 = rn_tf32(0.5f * v0 * (1.0f + erff(v0 * inv_s2)));
                    v1 = rn_tf32(0.5f * v1 * (1.0f + erff(v1 * inv_s2)));
                } else if (MODE == 2) {
                    float2 rv = *reinterpret_cast<const float2*>(
                        Res + (size_t)m * N + n);
                    v0 += rv.x; v1 += rv.y;
                } else if (MODE == 3) {
                    v0 = rn_tf32(v0); v1 = rn_tf32(v1);
                }
                float2 o2 = make_float2(v0, v1);
                *reinterpret_cast<float2*>(C + (size_t)m * N + n) = o2;
            }
        }
    }
}

// ---------------------------------------------------------------------------
// Flash attention on tensor cores (tf32 mma.sync), HD=64, T=1024.
// Block: 128 threads (4 warps), 64 queries; warp owns 16 q-rows.
// Per 64-key tile: scores mma -> online softmax in C-frag registers ->
// P (rn_tf32) to per-warp smem -> PV mma with V staged transposed.
// Row pitch 68 floats: frag LDS conflict-free, rows 272B (16B aligned).
// ---------------------------------------------------------------------------
#define APITCH 68
#define ATILE (64 * APITCH)               // floats per 64-row tile
#define ASMEM_BYTES (4 * ATILE * 4)       // sQ, sK, sVt, sP(4 warps x 16 rows)

__global__ __launch_bounds__(128)
void attn_tc_kernel(const float* __restrict__ Q,
                    const float* __restrict__ K,
                    const float* __restrict__ V,
                    float* __restrict__ O)
{
    extern __shared__ float sm[];
    float* sQ  = sm;
    float* sK  = sm + ATILE;
    float* sVt = sm + 2 * ATILE;
    float* sP  = sm + 3 * ATILE;

    const int bh = blockIdx.x;
    const int b  = bh / HH;
    const int h  = bh % HH;
    const int q0 = blockIdx.y * 64;
    const size_t base = (size_t)b * TT * DD + (size_t)h * HD;

    const int tid = threadIdx.x;
    const int warp = tid >> 5, lane = tid & 31;
    const int lr = lane >> 2, lc = lane & 3;
    const int qr = warp * 16;

    // stage Q tile [64 q][64 d]
    for (int i = tid; i < 64 * 16; i += 128) {
        const int r = i >> 4, c4 = (i & 15) << 2;
        float4 qv = *reinterpret_cast<const float4*>(
            Q + base + (size_t)(q0 + r) * DD + c4);
        *reinterpret_cast<float4*>(sQ + r * APITCH + c4) = qv;
    }

    float m0 = -INFINITY, m1 = -INFINITY;
    float l0 = 0.0f, l1 = 0.0f;
    float o[8][4];
#pragma unroll
    for (int nt = 0; nt < 8; nt++)
#pragma unroll
        for (int j = 0; j < 4; j++) o[nt][j] = 0.0f;

    for (int t0 = 0; t0 < TT; t0 += 64) {
        __syncthreads();
        // stage K [key][d] and V transposed [d][key]
        for (int i = tid; i < 64 * 16; i += 128) {
            const int r = i >> 4, c4 = (i & 15) << 2;
            float4 kv = *reinterpret_cast<const float4*>(
                K + base + (size_t)(t0 + r) * DD + c4);
            *reinterpret_cast<float4*>(sK + r * APITCH + c4) = kv;
            float4 vv = *reinterpret_cast<const float4*>(
                V + base + (size_t)(t0 + r) * DD + c4);
            sVt[(c4 + 0) * APITCH + r] = vv.x;
            sVt[(c4 + 1) * APITCH + r] = vv.y;
            sVt[(c4 + 2) * APITCH + r] = vv.z;
            sVt[(c4 + 3) * APITCH + r] = vv.w;
        }
        __syncthreads();

        // scores: 16 q-rows x 64 keys
        float s[8][4];
#pragma unroll
        for (int nt = 0; nt < 8; nt++)
#pragma unroll
            for (int j = 0; j < 4; j++) s[nt][j] = 0.0f;

        const uint32_t* uQ = reinterpret_cast<const uint32_t*>(sQ);
        const uint32_t* uK = reinterpret_cast<const uint32_t*>(sK);
#pragma unroll
        for (int kk = 0; kk < 64; kk += 8) {
            uint32_t a[4];
            a[0] = uQ[(qr + lr) * APITCH + kk + lc];
            a[1] = uQ[(qr + lr + 8) * APITCH + kk + lc];
            a[2] = uQ[(qr + lr) * APITCH + kk + lc + 4];
            a[3] = uQ[(qr + lr + 8) * APITCH + kk + lc + 4];
#pragma unroll
            for (int nt = 0; nt < 8; nt++) {
                uint32_t bf[2];
                bf[0] = uK[(nt * 8 + lr) * APITCH + kk + lc];
                bf[1] = uK[(nt * 8 + lr) * APITCH + kk + lc + 4];
                mma_tf32(s[nt], a, bf);
            }
        }

        // scale + row max (rows lr / lr+8)
        float mx0 = -INFINITY, mx1 = -INFINITY;
#pragma unroll
        for (int nt = 0; nt < 8; nt++) {
            s[nt][0] *= 0.125f; s[nt][1] *= 0.125f;
            s[nt][2] *= 0.125f; s[nt][3] *= 0.125f;
            mx0 = fmaxf(mx0, fmaxf(s[nt][0], s[nt][1]));
            mx1 = fmaxf(mx1, fmaxf(s[nt][2], s[nt][3]));
        }
        mx0 = fmaxf(mx0, __shfl_xor_sync(0xffffffffu, mx0, 1));
        mx0 = fmaxf(mx0, __shfl_xor_sync(0xffffffffu, mx0, 2));
        mx1 = fmaxf(mx1, __shfl_xor_sync(0xffffffffu, mx1, 1));
        mx1 = fmaxf(mx1, __shfl_xor_sync(0xffffffffu, mx1, 2));

        const float nm0 = fmaxf(m0, mx0), nm1 = fmaxf(m1, mx1);
        const float corr0 = __expf(m0 - nm0), corr1 = __expf(m1 - nm1);
        m0 = nm0; m1 = nm1;

        float ls0 = 0.0f, ls1 = 0.0f;
#pragma unroll
        for (int nt = 0; nt < 8; nt++) {
            s[nt][0] = __expf(s[nt][0] - nm0);
            s[nt][1] = __expf(s[nt][1] - nm0);
            s[nt][2] = __expf(s[nt][2] - nm1);
            s[nt][3] = __expf(s[nt][3] - nm1);
            ls0 += s[nt][0] + s[nt][1];
            ls1 += s[nt][2] + s[nt][3];
        }
        ls0 += __shfl_xor_sync(0xffffffffu, ls0, 1);
        ls0 += __shfl_xor_sync(0xffffffffu, ls0, 2);
        ls1 += __shfl_xor_sync(0xffffffffu, ls1, 1);
        ls1 += __shfl_xor_sync(0xffffffffu, ls1, 2);
        l0 = l0 * corr0 + ls0;
        l1 = l1 * corr1 + ls1;

#pragma unroll
        for (int nt = 0; nt < 8; nt++) {
            o[nt][0] *= corr0; o[nt][1] *= corr0;
            o[nt][2] *= corr1; o[nt][3] *= corr1;
        }

        // P -> per-warp smem (tf32 RN)
        float* pw = sP + warp * 16 * APITCH;
#pragma unroll
        for (int nt = 0; nt < 8; nt++) {
            pw[lr * APITCH + nt * 8 + 2 * lc]           = rn_tf32(s[nt][0]);
            pw[lr * APITCH + nt * 8 + 2 * lc + 1]       = rn_tf32(s[nt][1]);
            pw[(lr + 8) * APITCH + nt * 8 + 2 * lc]     = rn_tf32(s[nt][2]);
            pw[(lr + 8) * APITCH + nt * 8 + 2 * lc + 1] = rn_tf32(s[nt][3]);
        }
        __syncwarp();

        // PV: O += P @ V  (K = 64 keys)
        const uint32_t* uP = reinterpret_cast<const uint32_t*>(pw);
        const uint32_t* uV = reinterpret_cast<const uint32_t*>(sVt);
#pragma unroll
        for (int kk = 0; kk < 64; kk += 8) {
            uint32_t a[4];
            a[0] = uP[lr * APITCH + kk + lc];
            a[1] = uP[(lr + 8) * APITCH + kk + lc];
            a[2] = uP[lr * APITCH + kk + lc + 4];
            a[3] = uP[(lr + 8) * APITCH + kk + lc + 4];
#pragma unroll
            for (int nt = 0; nt < 8; nt++) {
                uint32_t bf[2];
                bf[0] = uV[(nt * 8 + lr) * APITCH + kk + lc];
                bf[1] = uV[(nt * 8 + lr) * APITCH + kk + lc + 4];
                mma_tf32(o[nt], a, bf);
            }
        }
        __syncwarp();
    }

    // write ctx (tf32 RN for the Wo GEMM)
    const float inv0 = 1.0f / l0, inv1 = 1.0f / l1;
    const size_t row0 = base + (size_t)(q0 + qr + lr) * DD;
    const size_t row1 = base + (size_t)(q0 + qr + lr + 8) * DD;
#pragma unroll
    for (int nt = 0; nt < 8; nt++) {
        const int col = nt * 8 + 2 * lc;
        float2 v0 = make_float2(rn_tf32(o[nt][0] * inv0), rn_tf32(o[nt][1] * inv0));
        float2 v1 = make_float2(rn_tf32(o[nt][2] * inv1), rn_tf32(o[nt][3] * inv1));
        *reinterpret_cast<float2*>(O + row0 + col) = v0;
        *reinterpret_cast<float2*>(O + row1 + col) = v1;
    }
}

// ---------------------------------------------------------------------------
// Launch
// ---------------------------------------------------------------------------
static float* sym(const void* symbol)
{
    void* p = nullptr;
    cudaGetSymbolAddress(&p, symbol);
    return reinterpret_cast<float*>(p);
}

extern "C" void kernel_launch(void* const* d_in, const int* in_sizes, int n_in,
                              void* d_out, int out_size)
{
    const float* x  = (const float*)d_in[0];
    const float* Wq = (const float*)d_in[1];  const float* bq = (const float*)d_in[2];
    const float* Wk = (const float*)d_in[3];  const float* bk = (const float*)d_in[4];
    const float* Wv = (const float*)d_in[5];  const float* bv = (const float*)d_in[6];
    const float* Wo = (const float*)d_in[7];  const float* bo = (const float*)d_in[8];
    const float* W1 = (const float*)d_in[9];  const float* b1 = (const float*)d_in[10];
    const float* W2 = (const float*)d_in[11]; const float* b2 = (const float*)d_in[12];
    const float* g1 = (const float*)d_in[13]; const float* be1 = (const float*)d_in[14];
    const float* g2 = (const float*)d_in[15]; const float* be2 = (const float*)d_in[16];
    float* out = (float*)d_out;

    float* hln1  = sym(g_hln1);
    float* hln1t = sym(g_hln1t);
    float* qb    = sym(g_q);
    float* kb    = sym(g_k);
    float* vb    = sym(g_v);
    float* ctx   = sym(g_ctx);
    float* hb    = sym(g_h);
    float* h2b   = sym(g_h2);
    float* h2t   = sym(g_h2t);
    float* ffb   = sym(g_ff);
    float* WqT = sym(g_WqT); float* WkT = sym(g_WkT);
    float* WvT = sym(g_WvT); float* WoT = sym(g_WoT);
    float* W1T = sym(g_W1T); float* W2T = sym(g_W2T);

    cudaFuncSetAttribute(gemm_mma<1>, cudaFuncAttributeMaxDynamicSharedMemorySize, GSMEM_BYTES);
    cudaFuncSetAttribute(gemm_mma<2>, cudaFuncAttributeMaxDynamicSharedMemorySize, GSMEM_BYTES);
    cudaFuncSetAttribute(gemm_mma<3>, cudaFuncAttributeMaxDynamicSharedMemorySize, GSMEM_BYTES);
    cudaFuncSetAttribute(attn_tc_kernel, cudaFuncAttributeMaxDynamicSharedMemorySize, ASMEM_BYTES);

    // weight transposes (+ tf32 RN)
    {
        dim3 thr(32, 8);
        transpose_rn_kernel<<<dim3(DD / 32, DD / 32), thr>>>(Wq, WqT, DD, DD);
        transpose_rn_kernel<<<dim3(DD / 32, DD / 32), thr>>>(Wk, WkT, DD, DD);
        transpose_rn_kernel<<<dim3(DD / 32, DD / 32), thr>>>(Wv, WvT, DD, DD);
        transpose_rn_kernel<<<dim3(DD / 32, DD / 32), thr>>>(Wo, WoT, DD, DD);
        transpose_rn_kernel<<<dim3(FF / 32, DD / 32), thr>>>(W1, W1T, DD, FF);
        transpose_rn_kernel<<<dim3(DD / 32, FF / 32), thr>>>(W2, W2T, FF, DD);
    }

    // 1. LN1 (fp32 + tf32 copies)
    ln_kernel<<<MROWS, 256>>>(x, g1, be1, hln1, hln1t);

    // 2. QKV projections — outputs tf32-rounded for the attention MMAs
    {
        dim3 grid(DD / 128, MROWS / 128);
        gemm_mma<3><<<grid, 256, GSMEM_BYTES>>>(hln1t, WqT, bq, qb, nullptr, MROWS, DD, DD);
        gemm_mma<3><<<grid, 256, GSMEM_BYTES>>>(hln1t, WkT, bk, kb, nullptr, MROWS, DD, DD);
        gemm_mma<3><<<grid, 256, GSMEM_BYTES>>>(hln1t, WvT, bv, vb, nullptr, MROWS, DD, DD);
    }

    // 3. attention (tensor-core flash attention)
    {
        dim3 grid(BB * HH, TT / 64);
        attn_tc_kernel<<<grid, 128, ASMEM_BYTES>>>(qb, kb, vb, ctx);
    }

    // 4. output projection + residual
    {
        dim3 grid(DD / 128, MROWS / 128);
        gemm_mma<2><<<grid, 256, GSMEM_BYTES>>>(ctx, WoT, bo, hb, hln1, MROWS, DD, DD);
    }

    // 5. LN2
    ln_kernel<<<MROWS, 256>>>(hb, g2, be2, h2b, h2t);

    // 6. FFN up + exact GELU (output tf32-rounded)
    {
        dim3 grid(FF / 128, MROWS / 128);
        gemm_mma<1><<<grid, 256, GSMEM_BYTES>>>(h2t, W1T, b1, ffb, nullptr, MROWS, FF, DD);
    }

    // 7. FFN down + bias + residual -> out
    {
        dim3 grid(DD / 128, MROWS / 128);
        gemm_mma<2><<<grid, 256, GSMEM_BYTES>>>(ffb, W2T, b2, out, h2b, MROWS, DD, FF);
    }
}

// round 5
// speedup vs baseline: 5.6562x; 1.4831x over previous
#include <cuda_runtime.h>
#include <cuda_fp16.h>
#include <math.h>
#include <stdint.h>

// ---------------------------------------------------------------------------
// Problem constants
// ---------------------------------------------------------------------------
#define BB 8
#define TT 1024
#define DD 1024
#define HH 16
#define HD 64
#define FF 4096
#define MROWS (BB * TT)          // 8192
#define LN_EPS 1e-5f

// ---------------------------------------------------------------------------
// Scratch (__device__ globals; allocation-free rule)
// ---------------------------------------------------------------------------
__device__ float  g_hln1 [MROWS * DD];   // fp32 residual
__device__ __half g_hln1t[MROWS * DD];   // half LN1 for GEMM A
__device__ __half g_q    [MROWS * DD];
__device__ __half g_k    [MROWS * DD];
__device__ __half g_v    [MROWS * DD];
__device__ __half g_ctx  [MROWS * DD];
__device__ float  g_h    [MROWS * DD];   // h after attn residual (fp32)
__device__ float  g_h2   [MROWS * DD];   // LN2 out fp32 (residual for out)
__device__ __half g_h2t  [MROWS * DD];
__device__ __half g_ff   [MROWS * FF];
__device__ __half g_WqT  [DD * DD];
__device__ __half g_WkT  [DD * DD];
__device__ __half g_WvT  [DD * DD];
__device__ __half g_WoT  [DD * DD];
__device__ __half g_W1T  [FF * DD];
__device__ __half g_W2T  [DD * FF];

// ---------------------------------------------------------------------------
// Helpers
// ---------------------------------------------------------------------------
__device__ __forceinline__ uint32_t smem_u32(const void* p) {
    uint32_t a;
    asm("{ .reg .u64 t; cvta.to.shared.u64 t, %1; cvt.u32.u64 %0, t; }"
        : "=r"(a) : "l"(p));
    return a;
}

__device__ __forceinline__ void cp_async16(uint32_t saddr, const void* gaddr) {
    asm volatile("cp.async.cg.shared.global [%0], [%1], 16;\n"
                 :: "r"(saddr), "l"(gaddr) : "memory");
}
#define CP_COMMIT() asm volatile("cp.async.commit_group;\n" ::: "memory")

// fp16 mma with fp32 accumulate
__device__ __forceinline__ void mma_f16(float c[4], const uint32_t a[4],
                                        const uint32_t b[2]) {
    asm volatile(
        "mma.sync.aligned.m16n8k16.row.col.f32.f16.f16.f32 "
        "{%0,%1,%2,%3}, {%4,%5,%6,%7}, {%8,%9}, {%0,%1,%2,%3};"
        : "+f"(c[0]), "+f"(c[1]), "+f"(c[2]), "+f"(c[3])
        : "r"(a[0]), "r"(a[1]), "r"(a[2]), "r"(a[3]),
          "r"(b[0]), "r"(b[1]));
}

__device__ __forceinline__ void ldsm_x4_trans(uint32_t r[4], uint32_t saddr) {
    asm volatile(
        "ldmatrix.sync.aligned.m8n8.x4.trans.shared.b16 {%0,%1,%2,%3}, [%4];"
        : "=r"(r[0]), "=r"(r[1]), "=r"(r[2]), "=r"(r[3])
        : "r"(saddr));
}

// ---------------------------------------------------------------------------
// Weight transpose + half convert: out[N,K] = half(in[K,N]^T)
// ---------------------------------------------------------------------------
__global__ void transpose_h_kernel(const float* __restrict__ in,
                                   __half* __restrict__ out, int K, int N)
{
    __shared__ float t[32][33];
    const int n0 = blockIdx.x * 32, k0 = blockIdx.y * 32;
    for (int i = threadIdx.y; i < 32; i += 8)
        t[i][threadIdx.x] = in[(size_t)(k0 + i) * N + n0 + threadIdx.x];
    __syncthreads();
    for (int i = threadIdx.y; i < 32; i += 8)
        out[(size_t)(n0 + i) * K + k0 + threadIdx.x] =
            __float2half_rn(t[threadIdx.x][i]);
}

// ---------------------------------------------------------------------------
// LayerNorm (unbiased var, ddof=1), dual output: fp32 + half
// ---------------------------------------------------------------------------
__global__ void ln_kernel(const float* __restrict__ src,
                          const float* __restrict__ gamma,
                          const float* __restrict__ beta,
                          float* __restrict__ dst,
                          __half* __restrict__ dsth)
{
    const int row = blockIdx.x;
    const int tid = threadIdx.x;
    const float4* in4 = reinterpret_cast<const float4*>(src + (size_t)row * DD);
    float4* out4 = reinterpret_cast<float4*>(dst + (size_t)row * DD);
    __half2* outh = reinterpret_cast<__half2*>(dsth + (size_t)row * DD);
    const float4* g4 = reinterpret_cast<const float4*>(gamma);
    const float4* b4 = reinterpret_cast<const float4*>(beta);

    float4 x = in4[tid];
    float s  = x.x + x.y + x.z + x.w;
    float ss = x.x * x.x + x.y * x.y + x.z * x.z + x.w * x.w;
    for (int o = 16; o; o >>= 1) {
        s  += __shfl_xor_sync(0xffffffffu, s, o);
        ss += __shfl_xor_sync(0xffffffffu, ss, o);
    }
    __shared__ float rs[8], rss[8];
    __shared__ float smean, srstd;
    const int warp = tid >> 5, lane = tid & 31;
    if (lane == 0) { rs[warp] = s; rss[warp] = ss; }
    __syncthreads();
    if (warp == 0) {
        float a = (lane < 8) ? rs[lane] : 0.0f;
        float b = (lane < 8) ? rss[lane] : 0.0f;
        for (int o = 4; o; o >>= 1) {
            a += __shfl_xor_sync(0xffffffffu, a, o);
            b += __shfl_xor_sync(0xffffffffu, b, o);
        }
        if (lane == 0) {
            float mean = a * (1.0f / DD);
            float var  = (b - (float)DD * mean * mean) * (1.0f / (DD - 1));
            smean = mean;
            srstd = rsqrtf(var + LN_EPS);
        }
    }
    __syncthreads();
    const float mean = smean, rstd = srstd;
    float4 gv = g4[tid], bv = b4[tid];
    float4 o;
    o.x = (x.x - mean) * rstd * gv.x + bv.x;
    o.y = (x.y - mean) * rstd * gv.y + bv.y;
    o.z = (x.z - mean) * rstd * gv.z + bv.z;
    o.w = (x.w - mean) * rstd * gv.w + bv.w;
    out4[tid] = o;
    outh[2 * tid]     = __floats2half2_rn(o.x, o.y);
    outh[2 * tid + 1] = __floats2half2_rn(o.z, o.w);
}

// ---------------------------------------------------------------------------
// fp16 mma GEMM: C[M,N] = A[M,K] @ B^T (B [N,K] K-major, half) + bias
// MODE 0: half out, +bias (QKV)
// MODE 1: half out, gelu(acc+bias) (FFN1)
// MODE 2: float out, acc+bias+Res (Wo, FFN2)
// 128x128 tile, K-chunk 64 halves (4 ksteps of 16), 2-stage cp.async.
// Smem rows: 64 data halves padded to 144B pitch (conflict-free frag LDS).
// ---------------------------------------------------------------------------
#define GP2 36                        // row pitch in half2 (b32) units
#define GTILE_B (128 * 144)           // 18432 B per operand tile
#define GSTAGE_B (2 * GTILE_B)        // 36864 (A then B)
#define GSMEM_B (2 * GSTAGE_B)        // 73728

template <int MODE>
__global__ __launch_bounds__(256, 2)
void gemm_h(const __half* __restrict__ A, const __half* __restrict__ B,
            const float* __restrict__ bias, void* __restrict__ Cv,
            const float* __restrict__ Res, int M, int N, int K)
{
    extern __shared__ char dynsmem[];
    const int tid = threadIdx.x;
    const int wid = tid >> 5, lane = tid & 31;
    const int bx = blockIdx.x, by = blockIdx.y;

    const int warp_m = (wid & 3) * 32;
    const int warp_n = (wid >> 2) * 64;
    const int lr = lane >> 2;
    const int lc = lane & 3;

    const uint32_t sbase = smem_u32(dynsmem);

    // staging plan: row = tid/2, half-row select = tid&1 (64B each), 4x16B
    const int g_r  = tid >> 1;
    const int g_h  = tid & 1;
    const __half* gA = A + (size_t)(by * 128 + g_r) * K + g_h * 32;
    const __half* gB = B + (size_t)(bx * 128 + g_r) * K + g_h * 32;
    const uint32_t s_off = (uint32_t)(g_r * 144 + g_h * 64);

    const int NITER = K >> 6;

    auto stage = [&](int s) {
        const uint32_t base = sbase + (uint32_t)(s & 1) * GSTAGE_B;
        const int k0 = s << 6;
#pragma unroll
        for (int p = 0; p < 4; p++) {
            cp_async16(base + s_off + p * 16, gA + k0 + p * 8);
            cp_async16(base + GTILE_B + s_off + p * 16, gB + k0 + p * 8);
        }
        CP_COMMIT();
    };

    float c[2][8][4];
#pragma unroll
    for (int mt = 0; mt < 2; mt++)
#pragma unroll
        for (int nt = 0; nt < 8; nt++)
#pragma unroll
            for (int r = 0; r < 4; r++) c[mt][nt][r] = 0.0f;

    stage(0);
    if (NITER > 1) stage(1);

    for (int i = 0; i < NITER; i++) {
        if (i < NITER - 1)
            asm volatile("cp.async.wait_group 1;\n" ::: "memory");
        else
            asm volatile("cp.async.wait_group 0;\n" ::: "memory");
        __syncthreads();

        const uint32_t* As = reinterpret_cast<const uint32_t*>(
            dynsmem + (size_t)(i & 1) * GSTAGE_B);
        const uint32_t* Bs = reinterpret_cast<const uint32_t*>(
            dynsmem + (size_t)(i & 1) * GSTAGE_B + GTILE_B);

#pragma unroll
        for (int ks = 0; ks < 4; ks++) {
            const int kk2 = ks * 8;
            uint32_t a[2][4];
#pragma unroll
            for (int mt = 0; mt < 2; mt++) {
                const int r0 = warp_m + mt * 16 + lr;
                a[mt][0] = As[r0 * GP2 + kk2 + lc];
                a[mt][1] = As[(r0 + 8) * GP2 + kk2 + lc];
                a[mt][2] = As[r0 * GP2 + kk2 + lc + 4];
                a[mt][3] = As[(r0 + 8) * GP2 + kk2 + lc + 4];
            }
            uint32_t b[8][2];
#pragma unroll
            for (int nt = 0; nt < 8; nt++) {
                const int n0 = warp_n + nt * 8 + lr;
                b[nt][0] = Bs[n0 * GP2 + kk2 + lc];
                b[nt][1] = Bs[n0 * GP2 + kk2 + lc + 4];
            }
#pragma unroll
            for (int mt = 0; mt < 2; mt++)
#pragma unroll
                for (int nt = 0; nt < 8; nt++)
                    mma_f16(c[mt][nt], a[mt], b[nt]);
        }

        if (i + 2 < NITER) {
            __syncthreads();
            stage(i + 2);
        }
    }

    const float inv_s2 = 0.70710678118654752f;
    __half* Ch = reinterpret_cast<__half*>(Cv);
    float* Cf = reinterpret_cast<float*>(Cv);
#pragma unroll
    for (int mt = 0; mt < 2; mt++) {
#pragma unroll
        for (int rh = 0; rh < 2; rh++) {
            const int m = by * 128 + warp_m + mt * 16 + lr + rh * 8;
#pragma unroll
            for (int nt = 0; nt < 8; nt++) {
                const int n = bx * 128 + warp_n + nt * 8 + 2 * lc;
                float v0 = c[mt][nt][rh * 2 + 0] + bias[n];
                float v1 = c[mt][nt][rh * 2 + 1] + bias[n + 1];
                if (MODE == 1) {
                    v0 = 0.5f * v0 * (1.0f + erff(v0 * inv_s2));
                    v1 = 0.5f * v1 * (1.0f + erff(v1 * inv_s2));
                }
                if (MODE == 2) {
                    float2 rv = *reinterpret_cast<const float2*>(
                        Res + (size_t)m * N + n);
                    v0 += rv.x; v1 += rv.y;
                    *reinterpret_cast<float2*>(Cf + (size_t)m * N + n) =
                        make_float2(v0, v1);
                } else {
                    *reinterpret_cast<__half2*>(Ch + (size_t)m * N + n) =
                        __floats2half2_rn(v0, v1);
                }
            }
        }
    }
}

// ---------------------------------------------------------------------------
// fp16 flash attention, HD=64, T=1024.
// 128 threads / 4 warps, 64 queries per block, warp owns 16 q rows.
// Scores: scalar half2 frags (Q A-op, K B-op). PV: ldmatrix.x4.trans on V.
// Rows padded to 144B (36 half2) -> conflict-free.
// ---------------------------------------------------------------------------
#define AP2 36
#define AT_H2 (64 * AP2)                  // half2 per 64-row tile
#define ASMEM_B (4 * AT_H2 * 4)           // sQ, sK, sV, sP = 36864 B

__global__ __launch_bounds__(128)
void attn_h_kernel(const __half* __restrict__ Q,
                   const __half* __restrict__ K,
                   const __half* __restrict__ V,
                   __half* __restrict__ O)
{
    __shared__ uint32_t sm[4 * AT_H2];
    uint32_t* uQ = sm;
    uint32_t* uK = sm + AT_H2;
    uint32_t* uV = sm + 2 * AT_H2;

    const int bh = blockIdx.x;
    const int b  = bh / HH;
    const int h  = bh % HH;
    const int q0 = blockIdx.y * 64;
    const size_t base = (size_t)b * TT * DD + (size_t)h * HD;

    const int tid = threadIdx.x;
    const int warp = tid >> 5, lane = tid & 31;
    const int lr = lane >> 2, lc = lane & 3;
    const int qr = warp * 16;
    uint32_t* uP = sm + 3 * AT_H2 + warp * 16 * AP2;
    const uint32_t sV_byte = smem_u32(sm + 2 * AT_H2);

    // stage Q tile: 64 rows x 128B
    {
        char* sQb = reinterpret_cast<char*>(sm);
        for (int i = tid; i < 512; i += 128) {
            const int r = i >> 3, cc = i & 7;
            *reinterpret_cast<uint4*>(sQb + r * 144 + cc * 16) =
                *reinterpret_cast<const uint4*>(
                    Q + base + (size_t)(q0 + r) * DD + cc * 8);
        }
    }

    float m0 = -INFINITY, m1 = -INFINITY;
    float l0 = 0.0f, l1 = 0.0f;
    float o[8][4];
#pragma unroll
    for (int nt = 0; nt < 8; nt++)
#pragma unroll
        for (int j = 0; j < 4; j++) o[nt][j] = 0.0f;

    for (int t0 = 0; t0 < TT; t0 += 64) {
        __syncthreads();
        {
            char* sKb = reinterpret_cast<char*>(uK);
            char* sVb = reinterpret_cast<char*>(uV);
            for (int i = tid; i < 512; i += 128) {
                const int r = i >> 3, cc = i & 7;
                *reinterpret_cast<uint4*>(sKb + r * 144 + cc * 16) =
                    *reinterpret_cast<const uint4*>(
                        K + base + (size_t)(t0 + r) * DD + cc * 8);
                *reinterpret_cast<uint4*>(sVb + r * 144 + cc * 16) =
                    *reinterpret_cast<const uint4*>(
                        V + base + (size_t)(t0 + r) * DD + cc * 8);
            }
        }
        __syncthreads();

        // scores: 16 q rows x 64 keys, k-dim = d (4 ksteps of 16)
        float s[8][4];
#pragma unroll
        for (int nt = 0; nt < 8; nt++)
#pragma unroll
            for (int j = 0; j < 4; j++) s[nt][j] = 0.0f;

#pragma unroll
        for (int ks = 0; ks < 4; ks++) {
            const int kk2 = ks * 8;
            uint32_t a[4];
            a[0] = uQ[(qr + lr) * AP2 + kk2 + lc];
            a[1] = uQ[(qr + lr + 8) * AP2 + kk2 + lc];
            a[2] = uQ[(qr + lr) * AP2 + kk2 + lc + 4];
            a[3] = uQ[(qr + lr + 8) * AP2 + kk2 + lc + 4];
#pragma unroll
            for (int nt = 0; nt < 8; nt++) {
                uint32_t bf[2];
                bf[0] = uK[(nt * 8 + lr) * AP2 + kk2 + lc];
                bf[1] = uK[(nt * 8 + lr) * AP2 + kk2 + lc + 4];
                mma_f16(s[nt], a, bf);
            }
        }

        float mx0 = -INFINITY, mx1 = -INFINITY;
#pragma unroll
        for (int nt = 0; nt < 8; nt++) {
            s[nt][0] *= 0.125f; s[nt][1] *= 0.125f;
            s[nt][2] *= 0.125f; s[nt][3] *= 0.125f;
            mx0 = fmaxf(mx0, fmaxf(s[nt][0], s[nt][1]));
            mx1 = fmaxf(mx1, fmaxf(s[nt][2], s[nt][3]));
        }
        mx0 = fmaxf(mx0, __shfl_xor_sync(0xffffffffu, mx0, 1));
        mx0 = fmaxf(mx0, __shfl_xor_sync(0xffffffffu, mx0, 2));
        mx1 = fmaxf(mx1, __shfl_xor_sync(0xffffffffu, mx1, 1));
        mx1 = fmaxf(mx1, __shfl_xor_sync(0xffffffffu, mx1, 2));

        const float nm0 = fmaxf(m0, mx0), nm1 = fmaxf(m1, mx1);
        const float corr0 = __expf(m0 - nm0), corr1 = __expf(m1 - nm1);
        m0 = nm0; m1 = nm1;

        float ls0 = 0.0f, ls1 = 0.0f;
#pragma unroll
        for (int nt = 0; nt < 8; nt++) {
            s[nt][0] = __expf(s[nt][0] - nm0);
            s[nt][1] = __expf(s[nt][1] - nm0);
            s[nt][2] = __expf(s[nt][2] - nm1);
            s[nt][3] = __expf(s[nt][3] - nm1);
            ls0 += s[nt][0] + s[nt][1];
            ls1 += s[nt][2] + s[nt][3];
        }
        ls0 += __shfl_xor_sync(0xffffffffu, ls0, 1);
        ls0 += __shfl_xor_sync(0xffffffffu, ls0, 2);
        ls1 += __shfl_xor_sync(0xffffffffu, ls1, 1);
        ls1 += __shfl_xor_sync(0xffffffffu, ls1, 2);
        l0 = l0 * corr0 + ls0;
        l1 = l1 * corr1 + ls1;

#pragma unroll
        for (int nt = 0; nt < 8; nt++) {
            o[nt][0] *= corr0; o[nt][1] *= corr0;
            o[nt][2] *= corr1; o[nt][3] *= corr1;
        }

        // P -> per-warp smem as half
#pragma unroll
        for (int nt = 0; nt < 8; nt++) {
            uint32_t p01, p23;
            __half2 h01 = __floats2half2_rn(s[nt][0], s[nt][1]);
            __half2 h23 = __floats2half2_rn(s[nt][2], s[nt][3]);
            p01 = *reinterpret_cast<uint32_t*>(&h01);
            p23 = *reinterpret_cast<uint32_t*>(&h23);
            uP[lr * AP2 + nt * 4 + lc] = p01;
            uP[(lr + 8) * AP2 + nt * 4 + lc] = p23;
        }
        __syncwarp();

        // PV: k-dim = keys (4 ksteps of 16); V B-frags via ldmatrix.trans
#pragma unroll
        for (int ks = 0; ks < 4; ks++) {
            const int kk2 = ks * 8;
            uint32_t a[4];
            a[0] = uP[lr * AP2 + kk2 + lc];
            a[1] = uP[(lr + 8) * AP2 + kk2 + lc];
            a[2] = uP[lr * AP2 + kk2 + lc + 4];
            a[3] = uP[(lr + 8) * AP2 + kk2 + lc + 4];
            const int key = ks * 16 + (lane & 7) + ((lane >> 3) & 1) * 8;
#pragma unroll
            for (int ntp = 0; ntp < 4; ntp++) {
                uint32_t r[4];
                const uint32_t addr = sV_byte + key * 144 +
                                      ntp * 32 + ((lane >> 4) & 1) * 16;
                ldsm_x4_trans(r, addr);
                uint32_t b0[2] = {r[0], r[1]};
                uint32_t b1[2] = {r[2], r[3]};
                mma_f16(o[2 * ntp], a, b0);
                mma_f16(o[2 * ntp + 1], a, b1);
            }
        }
        __syncwarp();
    }

    const float inv0 = 1.0f / l0, inv1 = 1.0f / l1;
    const size_t row0 = base + (size_t)(q0 + qr + lr) * DD;
    const size_t row1 = base + (size_t)(q0 + qr + lr + 8) * DD;
#pragma unroll
    for (int nt = 0; nt < 8; nt++) {
        const int col = nt * 8 + 2 * lc;
        *reinterpret_cast<__half2*>(O + row0 + col) =
            __floats2half2_rn(o[nt][0] * inv0, o[nt][1] * inv0);
        *reinterpret_cast<__half2*>(O + row1 + col) =
            __floats2half2_rn(o[nt][2] * inv1, o[nt][3] * inv1);
    }
}

// ---------------------------------------------------------------------------
// Launch
// ---------------------------------------------------------------------------
template <typename T>
static T* symT(const void* symbol)
{
    void* p = nullptr;
    cudaGetSymbolAddress(&p, symbol);
    return reinterpret_cast<T*>(p);
}

extern "C" void kernel_launch(void* const* d_in, const int* in_sizes, int n_in,
                              void* d_out, int out_size)
{
    const float* x  = (const float*)d_in[0];
    const float* Wq = (const float*)d_in[1];  const float* bq = (const float*)d_in[2];
    const float* Wk = (const float*)d_in[3];  const float* bk = (const float*)d_in[4];
    const float* Wv = (const float*)d_in[5];  const float* bv = (const float*)d_in[6];
    const float* Wo = (const float*)d_in[7];  const float* bo = (const float*)d_in[8];
    const float* W1 = (const float*)d_in[9];  const float* b1 = (const float*)d_in[10];
    const float* W2 = (const float*)d_in[11]; const float* b2 = (const float*)d_in[12];
    const float* g1 = (const float*)d_in[13]; const float* be1 = (const float*)d_in[14];
    const float* g2 = (const float*)d_in[15]; const float* be2 = (const float*)d_in[16];
    float* out = (float*)d_out;

    float*  hln1  = symT<float>(g_hln1);
    __half* hln1t = symT<__half>(g_hln1t);
    __half* qb    = symT<__half>(g_q);
    __half* kb    = symT<__half>(g_k);
    __half* vb    = symT<__half>(g_v);
    __half* ctx   = symT<__half>(g_ctx);
    float*  hb    = symT<float>(g_h);
    float*  h2b   = symT<float>(g_h2);
    __half* h2t   = symT<__half>(g_h2t);
    __half* ffb   = symT<__half>(g_ff);
    __half* WqT = symT<__half>(g_WqT); __half* WkT = symT<__half>(g_WkT);
    __half* WvT = symT<__half>(g_WvT); __half* WoT = symT<__half>(g_WoT);
    __half* W1T = symT<__half>(g_W1T); __half* W2T = symT<__half>(g_W2T);

    cudaFuncSetAttribute(gemm_h<0>, cudaFuncAttributeMaxDynamicSharedMemorySize, GSMEM_B);
    cudaFuncSetAttribute(gemm_h<1>, cudaFuncAttributeMaxDynamicSharedMemorySize, GSMEM_B);
    cudaFuncSetAttribute(gemm_h<2>, cudaFuncAttributeMaxDynamicSharedMemorySize, GSMEM_B);

    // weight transposes (fp32 -> half, [N][K])
    {
        dim3 thr(32, 8);
        transpose_h_kernel<<<dim3(DD / 32, DD / 32), thr>>>(Wq, WqT, DD, DD);
        transpose_h_kernel<<<dim3(DD / 32, DD / 32), thr>>>(Wk, WkT, DD, DD);
        transpose_h_kernel<<<dim3(DD / 32, DD / 32), thr>>>(Wv, WvT, DD, DD);
        transpose_h_kernel<<<dim3(DD / 32, DD / 32), thr>>>(Wo, WoT, DD, DD);
        transpose_h_kernel<<<dim3(FF / 32, DD / 32), thr>>>(W1, W1T, DD, FF);
        transpose_h_kernel<<<dim3(DD / 32, FF / 32), thr>>>(W2, W2T, FF, DD);
    }

    // 1. LN1 (fp32 + half copies)
    ln_kernel<<<MROWS, 256>>>(x, g1, be1, hln1, hln1t);

    // 2. QKV projections (fp16 tensor cores), outputs half
    {
        dim3 grid(DD / 128, MROWS / 128);
        gemm_h<0><<<grid, 256, GSMEM_B>>>(hln1t, WqT, bq, qb, nullptr, MROWS, DD, DD);
        gemm_h<0><<<grid, 256, GSMEM_B>>>(hln1t, WkT, bk, kb, nullptr, MROWS, DD, DD);
        gemm_h<0><<<grid, 256, GSMEM_B>>>(hln1t, WvT, bv, vb, nullptr, MROWS, DD, DD);
    }

    // 3. attention (fp16 tensor cores), outputs half ctx
    {
        dim3 grid(BB * HH, TT / 64);
        attn_h_kernel<<<grid, 128>>>(qb, kb, vb, ctx);
    }

    // 4. output projection + residual (fp32 out)
    {
        dim3 grid(DD / 128, MROWS / 128);
        gemm_h<2><<<grid, 256, GSMEM_B>>>(ctx, WoT, bo, hb, hln1, MROWS, DD, DD);
    }

    // 5. LN2
    ln_kernel<<<MROWS, 256>>>(hb, g2, be2, h2b, h2t);

    // 6. FFN up + exact GELU (half out)
    {
        dim3 grid(FF / 128, MROWS / 128);
        gemm_h<1><<<grid, 256, GSMEM_B>>>(h2t, W1T, b1, ffb, nullptr, MROWS, FF, DD);
    }

    // 7. FFN down + bias + residual -> out (fp32)
    {
        dim3 grid(DD / 128, MROWS / 128);
        gemm_h<2><<<grid, 256, GSMEM_B>>>(ffb, W2T, b2, out, h2b, MROWS, DD, FF);
    }
}

// round 6
// speedup vs baseline: 5.8313x; 1.0309x over previous
#include <cuda_runtime.h>
#include <cuda_fp16.h>
#include <math.h>
#include <stdint.h>

// ---------------------------------------------------------------------------
// Problem constants
// ---------------------------------------------------------------------------
#define BB 8
#define TT 1024
#define DD 1024
#define HH 16
#define HD 64
#define FF 4096
#define MROWS (BB * TT)          // 8192
#define QS (3 * DD)              // packed QKV row stride
#define LN_EPS 1e-5f

// ---------------------------------------------------------------------------
// Scratch (__device__ globals; allocation-free rule)
// ---------------------------------------------------------------------------
__device__ float  g_hln1 [MROWS * DD];     // fp32 residual
__device__ __half g_hln1t[MROWS * DD];     // half LN1 (GEMM A)
__device__ __half g_qkv  [MROWS * QS];     // packed Q|K|V halves
__device__ __half g_ctx  [MROWS * DD];
__device__ float  g_h    [MROWS * DD];     // after attn residual
__device__ float  g_h2   [MROWS * DD];     // LN2 fp32 (residual)
__device__ __half g_h2t  [MROWS * DD];
__device__ __half g_ff   [MROWS * FF];
__device__ __half g_Wqkv [3 * DD * DD];    // [3072][1024] K-major
__device__ __half g_WoT  [DD * DD];
__device__ __half g_W1T  [FF * DD];
__device__ __half g_W2T  [DD * FF];

// ---------------------------------------------------------------------------
// Helpers
// ---------------------------------------------------------------------------
__device__ __forceinline__ uint32_t smem_u32(const void* p) {
    uint32_t a;
    asm("{ .reg .u64 t; cvta.to.shared.u64 t, %1; cvt.u32.u64 %0, t; }"
        : "=r"(a) : "l"(p));
    return a;
}

__device__ __forceinline__ void cp_async16(uint32_t saddr, const void* gaddr) {
    asm volatile("cp.async.cg.shared.global [%0], [%1], 16;\n"
                 :: "r"(saddr), "l"(gaddr) : "memory");
}
#define CP_COMMIT() asm volatile("cp.async.commit_group;\n" ::: "memory")

__device__ __forceinline__ void mma_f16(float c[4], const uint32_t a[4],
                                        const uint32_t b[2]) {
    asm volatile(
        "mma.sync.aligned.m16n8k16.row.col.f32.f16.f16.f32 "
        "{%0,%1,%2,%3}, {%4,%5,%6,%7}, {%8,%9}, {%0,%1,%2,%3};"
        : "+f"(c[0]), "+f"(c[1]), "+f"(c[2]), "+f"(c[3])
        : "r"(a[0]), "r"(a[1]), "r"(a[2]), "r"(a[3]),
          "r"(b[0]), "r"(b[1]));
}

__device__ __forceinline__ void ldsm_x4_trans(uint32_t r[4], uint32_t saddr) {
    asm volatile(
        "ldmatrix.sync.aligned.m8n8.x4.trans.shared.b16 {%0,%1,%2,%3}, [%4];"
        : "=r"(r[0]), "=r"(r[1]), "=r"(r[2]), "=r"(r[3])
        : "r"(saddr));
}

// ---------------------------------------------------------------------------
// One kernel: transpose+half-convert ALL weights.
// tiles: Wq(1024) Wk(1024) Wv(1024) Wo(1024) W1(4096) W2(4096) = 12288
// ---------------------------------------------------------------------------
__global__ void transpose_all_kernel(const float* __restrict__ Wq,
                                     const float* __restrict__ Wk,
                                     const float* __restrict__ Wv,
                                     const float* __restrict__ Wo,
                                     const float* __restrict__ W1,
                                     const float* __restrict__ W2,
                                     __half* __restrict__ Wqkv,
                                     __half* __restrict__ WoT,
                                     __half* __restrict__ W1T,
                                     __half* __restrict__ W2T)
{
    __shared__ float t[32][33];
    const int tblk = blockIdx.x;

    const float* in; __half* out; int K, N, local;
    if (tblk < 3072) {            // Wq / Wk / Wv -> Wqkv rows seg*1024..
        const int seg = tblk >> 10;
        in  = (seg == 0) ? Wq : (seg == 1) ? Wk : Wv;
        out = Wqkv + (size_t)seg * DD * DD;
        K = DD; N = DD; local = tblk & 1023;
    } else if (tblk < 4096) {     // Wo
        in = Wo; out = WoT; K = DD; N = DD; local = tblk - 3072;
    } else if (tblk < 8192) {     // W1 [1024,4096] -> [4096][1024]
        in = W1; out = W1T; K = DD; N = FF; local = tblk - 4096;
    } else {                      // W2 [4096,1024] -> [1024][4096]
        in = W2; out = W2T; K = FF; N = DD; local = tblk - 8192;
    }
    const int ntn = N >> 5;
    const int n0 = (local % ntn) * 32;
    const int k0 = (local / ntn) * 32;

    for (int i = threadIdx.y; i < 32; i += 8)
        t[i][threadIdx.x] = in[(size_t)(k0 + i) * N + n0 + threadIdx.x];
    __syncthreads();
    for (int i = threadIdx.y; i < 32; i += 8)
        out[(size_t)(n0 + i) * K + k0 + threadIdx.x] =
            __float2half_rn(t[threadIdx.x][i]);
}

// ---------------------------------------------------------------------------
// LayerNorm (unbiased var, ddof=1), dual output: fp32 + half
// ---------------------------------------------------------------------------
__global__ void ln_kernel(const float* __restrict__ src,
                          const float* __restrict__ gamma,
                          const float* __restrict__ beta,
                          float* __restrict__ dst,
                          __half* __restrict__ dsth)
{
    const int row = blockIdx.x;
    const int tid = threadIdx.x;
    const float4* in4 = reinterpret_cast<const float4*>(src + (size_t)row * DD);
    float4* out4 = reinterpret_cast<float4*>(dst + (size_t)row * DD);
    __half2* outh = reinterpret_cast<__half2*>(dsth + (size_t)row * DD);
    const float4* g4 = reinterpret_cast<const float4*>(gamma);
    const float4* b4 = reinterpret_cast<const float4*>(beta);

    float4 x = in4[tid];
    float s  = x.x + x.y + x.z + x.w;
    float ss = x.x * x.x + x.y * x.y + x.z * x.z + x.w * x.w;
    for (int o = 16; o; o >>= 1) {
        s  += __shfl_xor_sync(0xffffffffu, s, o);
        ss += __shfl_xor_sync(0xffffffffu, ss, o);
    }
    __shared__ float rs[8], rss[8];
    __shared__ float smean, srstd;
    const int warp = tid >> 5, lane = tid & 31;
    if (lane == 0) { rs[warp] = s; rss[warp] = ss; }
    __syncthreads();
    if (warp == 0) {
        float a = (lane < 8) ? rs[lane] : 0.0f;
        float b = (lane < 8) ? rss[lane] : 0.0f;
        for (int o = 4; o; o >>= 1) {
            a += __shfl_xor_sync(0xffffffffu, a, o);
            b += __shfl_xor_sync(0xffffffffu, b, o);
        }
        if (lane == 0) {
            float mean = a * (1.0f / DD);
            float var  = (b - (float)DD * mean * mean) * (1.0f / (DD - 1));
            smean = mean;
            srstd = rsqrtf(var + LN_EPS);
        }
    }
    __syncthreads();
    const float mean = smean, rstd = srstd;
    float4 gv = g4[tid], bv = b4[tid];
    float4 o;
    o.x = (x.x - mean) * rstd * gv.x + bv.x;
    o.y = (x.y - mean) * rstd * gv.y + bv.y;
    o.z = (x.z - mean) * rstd * gv.z + bv.z;
    o.w = (x.w - mean) * rstd * gv.w + bv.w;
    out4[tid] = o;
    outh[2 * tid]     = __floats2half2_rn(o.x, o.y);
    outh[2 * tid + 1] = __floats2half2_rn(o.z, o.w);
}

// ---------------------------------------------------------------------------
// fp16 mma GEMM: C[M,N] = A[M,K] @ B^T (B [N,K] K-major, half) + bias
// MODE 0: half out, +bias
// MODE 1: half out, gelu(acc+bias)
// MODE 2: float out, acc+bias+Res
// MODE 3: half out, segmented bias (QKV: bias/bias2/bias3 per 1024-col seg)
// ---------------------------------------------------------------------------
#define GP2 36
#define GTILE_B (128 * 144)
#define GSTAGE_B (2 * GTILE_B)
#define GSMEM_B (2 * GSTAGE_B)

template <int MODE>
__global__ __launch_bounds__(256, 2)
void gemm_h(const __half* __restrict__ A, const __half* __restrict__ B,
            const float* __restrict__ bias, void* __restrict__ Cv,
            const float* __restrict__ Res,
            const float* __restrict__ bias2, const float* __restrict__ bias3,
            int M, int N, int K)
{
    extern __shared__ char dynsmem[];
    const int tid = threadIdx.x;
    const int wid = tid >> 5, lane = tid & 31;
    const int bx = blockIdx.x, by = blockIdx.y;

    const int warp_m = (wid & 3) * 32;
    const int warp_n = (wid >> 2) * 64;
    const int lr = lane >> 2;
    const int lc = lane & 3;

    const uint32_t sbase = smem_u32(dynsmem);

    const int g_r  = tid >> 1;
    const int g_h  = tid & 1;
    const __half* gA = A + (size_t)(by * 128 + g_r) * K + g_h * 32;
    const __half* gB = B + (size_t)(bx * 128 + g_r) * K + g_h * 32;
    const uint32_t s_off = (uint32_t)(g_r * 144 + g_h * 64);

    const int NITER = K >> 6;

    auto stage = [&](int s) {
        const uint32_t base = sbase + (uint32_t)(s & 1) * GSTAGE_B;
        const int k0 = s << 6;
#pragma unroll
        for (int p = 0; p < 4; p++) {
            cp_async16(base + s_off + p * 16, gA + k0 + p * 8);
            cp_async16(base + GTILE_B + s_off + p * 16, gB + k0 + p * 8);
        }
        CP_COMMIT();
    };

    float c[2][8][4];
#pragma unroll
    for (int mt = 0; mt < 2; mt++)
#pragma unroll
        for (int nt = 0; nt < 8; nt++)
#pragma unroll
            for (int r = 0; r < 4; r++) c[mt][nt][r] = 0.0f;

    stage(0);
    if (NITER > 1) stage(1);

    for (int i = 0; i < NITER; i++) {
        if (i < NITER - 1)
            asm volatile("cp.async.wait_group 1;\n" ::: "memory");
        else
            asm volatile("cp.async.wait_group 0;\n" ::: "memory");
        __syncthreads();

        const uint32_t* As = reinterpret_cast<const uint32_t*>(
            dynsmem + (size_t)(i & 1) * GSTAGE_B);
        const uint32_t* Bs = reinterpret_cast<const uint32_t*>(
            dynsmem + (size_t)(i & 1) * GSTAGE_B + GTILE_B);

#pragma unroll
        for (int ks = 0; ks < 4; ks++) {
            const int kk2 = ks * 8;
            uint32_t a[2][4];
#pragma unroll
            for (int mt = 0; mt < 2; mt++) {
                const int r0 = warp_m + mt * 16 + lr;
                a[mt][0] = As[r0 * GP2 + kk2 + lc];
                a[mt][1] = As[(r0 + 8) * GP2 + kk2 + lc];
                a[mt][2] = As[r0 * GP2 + kk2 + lc + 4];
                a[mt][3] = As[(r0 + 8) * GP2 + kk2 + lc + 4];
            }
            uint32_t b[8][2];
#pragma unroll
            for (int nt = 0; nt < 8; nt++) {
                const int n0 = warp_n + nt * 8 + lr;
                b[nt][0] = Bs[n0 * GP2 + kk2 + lc];
                b[nt][1] = Bs[n0 * GP2 + kk2 + lc + 4];
            }
#pragma unroll
            for (int mt = 0; mt < 2; mt++)
#pragma unroll
                for (int nt = 0; nt < 8; nt++)
                    mma_f16(c[mt][nt], a[mt], b[nt]);
        }

        if (i + 2 < NITER) {
            __syncthreads();
            stage(i + 2);
        }
    }

    // bias base for this 128-col block (segment-uniform: 1024 % 128 == 0)
    const float* bb = bias;
    if (MODE == 3) {
        const int seg = (bx * 128) >> 10;
        bb = (seg == 0) ? bias : (seg == 1) ? bias2 : bias3;
    }

    const float inv_s2 = 0.70710678118654752f;
    __half* Ch = reinterpret_cast<__half*>(Cv);
    float* Cf = reinterpret_cast<float*>(Cv);
#pragma unroll
    for (int mt = 0; mt < 2; mt++) {
#pragma unroll
        for (int rh = 0; rh < 2; rh++) {
            const int m = by * 128 + warp_m + mt * 16 + lr + rh * 8;
#pragma unroll
            for (int nt = 0; nt < 8; nt++) {
                const int n = bx * 128 + warp_n + nt * 8 + 2 * lc;
                const int nb = (MODE == 3) ? (n & 1023) : n;
                float v0 = c[mt][nt][rh * 2 + 0] + bb[nb];
                float v1 = c[mt][nt][rh * 2 + 1] + bb[nb + 1];
                if (MODE == 1) {
                    v0 = 0.5f * v0 * (1.0f + erff(v0 * inv_s2));
                    v1 = 0.5f * v1 * (1.0f + erff(v1 * inv_s2));
                }
                if (MODE == 2) {
                    float2 rv = *reinterpret_cast<const float2*>(
                        Res + (size_t)m * N + n);
                    v0 += rv.x; v1 += rv.y;
                    *reinterpret_cast<float2*>(Cf + (size_t)m * N + n) =
                        make_float2(v0, v1);
                } else {
                    *reinterpret_cast<__half2*>(Ch + (size_t)m * N + n) =
                        __floats2half2_rn(v0, v1);
                }
            }
        }
    }
}

// ---------------------------------------------------------------------------
// fp16 flash attention over packed QKV [M][3072], HD=64, T=1024.
// ---------------------------------------------------------------------------
#define AP2 36
#define AT_H2 (64 * AP2)

__global__ __launch_bounds__(128)
void attn_h_kernel(const __half* __restrict__ QKV,
                   __half* __restrict__ O)
{
    __shared__ uint32_t sm[4 * AT_H2];
    uint32_t* uQ = sm;
    uint32_t* uK = sm + AT_H2;
    uint32_t* uV = sm + 2 * AT_H2;

    const int bh = blockIdx.x;
    const int b  = bh / HH;
    const int h  = bh % HH;
    const int q0 = blockIdx.y * 64;
    const size_t baseq = (size_t)b * TT * QS + (size_t)h * HD;
    const size_t basek = baseq + DD;
    const size_t basev = baseq + 2 * DD;
    const size_t baseo = (size_t)b * TT * DD + (size_t)h * HD;

    const int tid = threadIdx.x;
    const int warp = tid >> 5, lane = tid & 31;
    const int lr = lane >> 2, lc = lane & 3;
    const int qr = warp * 16;
    uint32_t* uP = sm + 3 * AT_H2 + warp * 16 * AP2;
    const uint32_t sV_byte = smem_u32(sm + 2 * AT_H2);

    {
        char* sQb = reinterpret_cast<char*>(sm);
        for (int i = tid; i < 512; i += 128) {
            const int r = i >> 3, cc = i & 7;
            *reinterpret_cast<uint4*>(sQb + r * 144 + cc * 16) =
                *reinterpret_cast<const uint4*>(
                    QKV + baseq + (size_t)(q0 + r) * QS + cc * 8);
        }
    }

    float m0 = -INFINITY, m1 = -INFINITY;
    float l0 = 0.0f, l1 = 0.0f;
    float o[8][4];
#pragma unroll
    for (int nt = 0; nt < 8; nt++)
#pragma unroll
        for (int j = 0; j < 4; j++) o[nt][j] = 0.0f;

    for (int t0 = 0; t0 < TT; t0 += 64) {
        __syncthreads();
        {
            char* sKb = reinterpret_cast<char*>(uK);
            char* sVb = reinterpret_cast<char*>(uV);
            for (int i = tid; i < 512; i += 128) {
                const int r = i >> 3, cc = i & 7;
                *reinterpret_cast<uint4*>(sKb + r * 144 + cc * 16) =
                    *reinterpret_cast<const uint4*>(
                        QKV + basek + (size_t)(t0 + r) * QS + cc * 8);
                *reinterpret_cast<uint4*>(sVb + r * 144 + cc * 16) =
                    *reinterpret_cast<const uint4*>(
                        QKV + basev + (size_t)(t0 + r) * QS + cc * 8);
            }
        }
        __syncthreads();

        float s[8][4];
#pragma unroll
        for (int nt = 0; nt < 8; nt++)
#pragma unroll
            for (int j = 0; j < 4; j++) s[nt][j] = 0.0f;

#pragma unroll
        for (int ks = 0; ks < 4; ks++) {
            const int kk2 = ks * 8;
            uint32_t a[4];
            a[0] = uQ[(qr + lr) * AP2 + kk2 + lc];
            a[1] = uQ[(qr + lr + 8) * AP2 + kk2 + lc];
            a[2] = uQ[(qr + lr) * AP2 + kk2 + lc + 4];
            a[3] = uQ[(qr + lr + 8) * AP2 + kk2 + lc + 4];
#pragma unroll
            for (int nt = 0; nt < 8; nt++) {
                uint32_t bf[2];
                bf[0] = uK[(nt * 8 + lr) * AP2 + kk2 + lc];
                bf[1] = uK[(nt * 8 + lr) * AP2 + kk2 + lc + 4];
                mma_f16(s[nt], a, bf);
            }
        }

        float mx0 = -INFINITY, mx1 = -INFINITY;
#pragma unroll
        for (int nt = 0; nt < 8; nt++) {
            s[nt][0] *= 0.125f; s[nt][1] *= 0.125f;
            s[nt][2] *= 0.125f; s[nt][3] *= 0.125f;
            mx0 = fmaxf(mx0, fmaxf(s[nt][0], s[nt][1]));
            mx1 = fmaxf(mx1, fmaxf(s[nt][2], s[nt][3]));
        }
        mx0 = fmaxf(mx0, __shfl_xor_sync(0xffffffffu, mx0, 1));
        mx0 = fmaxf(mx0, __shfl_xor_sync(0xffffffffu, mx0, 2));
        mx1 = fmaxf(mx1, __shfl_xor_sync(0xffffffffu, mx1, 1));
        mx1 = fmaxf(mx1, __shfl_xor_sync(0xffffffffu, mx1, 2));

        const float nm0 = fmaxf(m0, mx0), nm1 = fmaxf(m1, mx1);
        const float corr0 = __expf(m0 - nm0), corr1 = __expf(m1 - nm1);
        m0 = nm0; m1 = nm1;

        float ls0 = 0.0f, ls1 = 0.0f;
#pragma unroll
        for (int nt = 0; nt < 8; nt++) {
            s[nt][0] = __expf(s[nt][0] - nm0);
            s[nt][1] = __expf(s[nt][1] - nm0);
            s[nt][2] = __expf(s[nt][2] - nm1);
            s[nt][3] = __expf(s[nt][3] - nm1);
            ls0 += s[nt][0] + s[nt][1];
            ls1 += s[nt][2] + s[nt][3];
        }
        ls0 += __shfl_xor_sync(0xffffffffu, ls0, 1);
        ls0 += __shfl_xor_sync(0xffffffffu, ls0, 2);
        ls1 += __shfl_xor_sync(0xffffffffu, ls1, 1);
        ls1 += __shfl_xor_sync(0xffffffffu, ls1, 2);
        l0 = l0 * corr0 + ls0;
        l1 = l1 * corr1 + ls1;

#pragma unroll
        for (int nt = 0; nt < 8; nt++) {
            o[nt][0] *= corr0; o[nt][1] *= corr0;
            o[nt][2] *= corr1; o[nt][3] *= corr1;
        }

#pragma unroll
        for (int nt = 0; nt < 8; nt++) {
            __half2 h01 = __floats2half2_rn(s[nt][0], s[nt][1]);
            __half2 h23 = __floats2half2_rn(s[nt][2], s[nt][3]);
            uP[lr * AP2 + nt * 4 + lc] = *reinterpret_cast<uint32_t*>(&h01);
            uP[(lr + 8) * AP2 + nt * 4 + lc] = *reinterpret_cast<uint32_t*>(&h23);
        }
        __syncwarp();

#pragma unroll
        for (int ks = 0; ks < 4; ks++) {
            const int kk2 = ks * 8;
            uint32_t a[4];
            a[0] = uP[lr * AP2 + kk2 + lc];
            a[1] = uP[(lr + 8) * AP2 + kk2 + lc];
            a[2] = uP[lr * AP2 + kk2 + lc + 4];
            a[3] = uP[(lr + 8) * AP2 + kk2 + lc + 4];
            const int key = ks * 16 + (lane & 7) + ((lane >> 3) & 1) * 8;
#pragma unroll
            for (int ntp = 0; ntp < 4; ntp++) {
                uint32_t r[4];
                const uint32_t addr = sV_byte + key * 144 +
                                      ntp * 32 + ((lane >> 4) & 1) * 16;
                ldsm_x4_trans(r, addr);
                uint32_t b0[2] = {r[0], r[1]};
                uint32_t b1[2] = {r[2], r[3]};
                mma_f16(o[2 * ntp], a, b0);
                mma_f16(o[2 * ntp + 1], a, b1);
            }
        }
        __syncwarp();
    }

    const float inv0 = 1.0f / l0, inv1 = 1.0f / l1;
    const size_t row0 = baseo + (size_t)(q0 + qr + lr) * DD;
    const size_t row1 = baseo + (size_t)(q0 + qr + lr + 8) * DD;
#pragma unroll
    for (int nt = 0; nt < 8; nt++) {
        const int col = nt * 8 + 2 * lc;
        *reinterpret_cast<__half2*>(O + row0 + col) =
            __floats2half2_rn(o[nt][0] * inv0, o[nt][1] * inv0);
        *reinterpret_cast<__half2*>(O + row1 + col) =
            __floats2half2_rn(o[nt][2] * inv1, o[nt][3] * inv1);
    }
}

// ---------------------------------------------------------------------------
// Launch
// ---------------------------------------------------------------------------
template <typename T>
static T* symT(const void* symbol)
{
    void* p = nullptr;
    cudaGetSymbolAddress(&p, symbol);
    return reinterpret_cast<T*>(p);
}

extern "C" void kernel_launch(void* const* d_in, const int* in_sizes, int n_in,
                              void* d_out, int out_size)
{
    const float* x  = (const float*)d_in[0];
    const float* Wq = (const float*)d_in[1];  const float* bq = (const float*)d_in[2];
    const float* Wk = (const float*)d_in[3];  const float* bk = (const float*)d_in[4];
    const float* Wv = (const float*)d_in[5];  const float* bv = (const float*)d_in[6];
    const float* Wo = (const float*)d_in[7];  const float* bo = (const float*)d_in[8];
    const float* W1 = (const float*)d_in[9];  const float* b1 = (const float*)d_in[10];
    const float* W2 = (const float*)d_in[11]; const float* b2 = (const float*)d_in[12];
    const float* g1 = (const float*)d_in[13]; const float* be1 = (const float*)d_in[14];
    const float* g2 = (const float*)d_in[15]; const float* be2 = (const float*)d_in[16];
    float* out = (float*)d_out;

    float*  hln1  = symT<float>(g_hln1);
    __half* hln1t = symT<__half>(g_hln1t);
    __half* qkv   = symT<__half>(g_qkv);
    __half* ctx   = symT<__half>(g_ctx);
    float*  hb    = symT<float>(g_h);
    float*  h2b   = symT<float>(g_h2);
    __half* h2t   = symT<__half>(g_h2t);
    __half* ffb   = symT<__half>(g_ff);
    __half* Wqkv = symT<__half>(g_Wqkv);
    __half* WoT  = symT<__half>(g_WoT);
    __half* W1T  = symT<__half>(g_W1T);
    __half* W2T  = symT<__half>(g_W2T);

    cudaFuncSetAttribute(gemm_h<1>, cudaFuncAttributeMaxDynamicSharedMemorySize, GSMEM_B);
    cudaFuncSetAttribute(gemm_h<2>, cudaFuncAttributeMaxDynamicSharedMemorySize, GSMEM_B);
    cudaFuncSetAttribute(gemm_h<3>, cudaFuncAttributeMaxDynamicSharedMemorySize, GSMEM_B);

    // 0. all weight transposes in one launch
    transpose_all_kernel<<<12288, dim3(32, 8)>>>(
        Wq, Wk, Wv, Wo, W1, W2, Wqkv, WoT, W1T, W2T);

    // 1. LN1 (fp32 + half)
    ln_kernel<<<MROWS, 256>>>(x, g1, be1, hln1, hln1t);

    // 2. fused QKV projection -> packed [M][3072]
    {
        dim3 grid(QS / 128, MROWS / 128);
        gemm_h<3><<<grid, 256, GSMEM_B>>>(hln1t, Wqkv, bq, qkv, nullptr,
                                          bk, bv, MROWS, QS, DD);
    }

    // 3. attention
    {
        dim3 grid(BB * HH, TT / 64);
        attn_h_kernel<<<grid, 128>>>(qkv, ctx);
    }

    // 4. output projection + residual (fp32 out)
    {
        dim3 grid(DD / 128, MROWS / 128);
        gemm_h<2><<<grid, 256, GSMEM_B>>>(ctx, WoT, bo, hb, hln1,
                                          nullptr, nullptr, MROWS, DD, DD);
    }

    // 5. LN2
    ln_kernel<<<MROWS, 256>>>(hb, g2, be2, h2b, h2t);

    // 6. FFN up + exact GELU (half out)
    {
        dim3 grid(FF / 128, MROWS / 128);
        gemm_h<1><<<grid, 256, GSMEM_B>>>(h2t, W1T, b1, ffb, nullptr,
                                          nullptr, nullptr, MROWS, FF, DD);
    }

    // 7. FFN down + bias + residual -> out (fp32)
    {
        dim3 grid(DD / 128, MROWS / 128);
        gemm_h<2><<<grid, 256, GSMEM_B>>>(ffb, W2T, b2, out, h2b,
                                          nullptr, nullptr, MROWS, DD, FF);
    }
}